// round 1
// baseline (speedup 1.0000x reference)
#include <cuda_runtime.h>
#include <math.h>

// ---------------------------------------------------------------------------
// Problem constants
// ---------------------------------------------------------------------------
#define NROW  16384          // B*L = 64*256
#define DMODEL 512
#define DFF   2048
#define LLEN  256
#define BB    64             // batch (also the "sequence" of the buggy attn)
#define HN    8
#define NSEG  (LLEN*HN*BB)   // 131072 (l,h,b) triples (but raw seg layout l*512+b*8+h)
#define SC2   (1.0f/64.0f)   // sc^2, sc = 1/sqrt(64)

// ---------------------------------------------------------------------------
// Scratch (static device arrays; no allocation allowed)
// ---------------------------------------------------------------------------
__device__ float g_xen [NROW*DMODEL];
__device__ float g_xde [NROW*DMODEL];
__device__ float g_q   [NROW*DMODEL];
__device__ float g_k   [NROW*DMODEL];
__device__ float g_v   [NROW*DMODEL];
__device__ float g_attn[NROW*DMODEL];
__device__ float g_bufA[NROW*DMODEL];
__device__ float g_bufB[NROW*DMODEL];
__device__ float g_enc [NROW*DMODEL];
__device__ float g_ffh [NROW*DFF];
__device__ float g_ffo [NROW*DMODEL];
__device__ float g_qs  [NSEG];
__device__ float g_ks  [NSEG];
__device__ float g_a2  [NSEG];        // layout [lh*64 + kk]
__device__ float g_s1  [LLEN*HN];

// ---------------------------------------------------------------------------
// Embed: x[r, :] = Xraw[r*64 .. r*64+63] @ W_in + B_in   (raw reshape of X)
// ---------------------------------------------------------------------------
__global__ void __launch_bounds__(128) k_embed(const float* __restrict__ X,
                                               const float* __restrict__ W,
                                               const float* __restrict__ b,
                                               float* __restrict__ out)
{
    __shared__ float xs[64];
    int r = blockIdx.x;
    int t = threadIdx.x;
    if (t < 64) xs[t] = X[(size_t)r*64 + t];
    __syncthreads();
#pragma unroll
    for (int i = 0; i < 4; i++) {
        int d = t + i*128;
        float acc = b[d];
#pragma unroll 16
        for (int c = 0; c < 64; c++) acc = fmaf(xs[c], W[c*512 + d], acc);
        out[(size_t)r*512 + d] = acc;
    }
}

// ---------------------------------------------------------------------------
// SGEMM: C[M,N] = A[M,K] @ B[K,N]  (+bias, +relu via flags)
// BM=BN=128, BK=8, 256 threads, 8x8 per thread. M%128==0, N%128==0, K%8==0.
// flags: bit0 = add bias, bit1 = relu
// ---------------------------------------------------------------------------
__global__ void __launch_bounds__(256) k_gemm(const float* __restrict__ A,
                                              const float* __restrict__ B,
                                              const float* __restrict__ bias,
                                              float* __restrict__ C,
                                              int M, int N, int K, int flags)
{
    __shared__ __align__(16) float As[8][128];
    __shared__ __align__(16) float Bs[8][128];

    int tid = threadIdx.x;
    int bm = blockIdx.y * 128;
    int bn = blockIdx.x * 128;
    int ty = tid >> 4;          // 0..15
    int tx = tid & 15;          // 0..15

    int arow = tid >> 1;        // 0..127
    int acol = (tid & 1) * 4;   // 0 or 4
    int brow = tid >> 5;        // 0..7
    int bcol = (tid & 31) * 4;  // 0..124

    const float* Aptr = A + (size_t)(bm + arow)*K + acol;
    const float* Bptr = B + (size_t)brow*N + bn + bcol;

    float acc[8][8];
#pragma unroll
    for (int i = 0; i < 8; i++)
#pragma unroll
        for (int j = 0; j < 8; j++) acc[i][j] = 0.f;

    for (int k0 = 0; k0 < K; k0 += 8) {
        float4 av = *(const float4*)(Aptr + k0);
        As[acol+0][arow] = av.x;
        As[acol+1][arow] = av.y;
        As[acol+2][arow] = av.z;
        As[acol+3][arow] = av.w;
        float4 bv = *(const float4*)(Bptr + (size_t)k0*N);
        *(float4*)&Bs[brow][bcol] = bv;
        __syncthreads();
#pragma unroll
        for (int k = 0; k < 8; k++) {
            float4 a0 = *(const float4*)&As[k][ty*8];
            float4 a1 = *(const float4*)&As[k][ty*8 + 4];
            float4 b0 = *(const float4*)&Bs[k][tx*8];
            float4 b1 = *(const float4*)&Bs[k][tx*8 + 4];
            float ra[8] = {a0.x,a0.y,a0.z,a0.w,a1.x,a1.y,a1.z,a1.w};
            float rb[8] = {b0.x,b0.y,b0.z,b0.w,b1.x,b1.y,b1.z,b1.w};
#pragma unroll
            for (int i = 0; i < 8; i++)
#pragma unroll
                for (int j = 0; j < 8; j++)
                    acc[i][j] = fmaf(ra[i], rb[j], acc[i][j]);
        }
        __syncthreads();
    }

#pragma unroll
    for (int i = 0; i < 8; i++) {
        size_t row = (size_t)(bm + ty*8 + i);
#pragma unroll
        for (int j = 0; j < 8; j++) {
            int col = bn + tx*8 + j;
            float v = acc[i][j];
            if (flags & 1) v += bias[col];
            if (flags & 2) v = fmaxf(v, 0.f);
            C[row*N + col] = v;
        }
    }
}

// ---------------------------------------------------------------------------
// Row-sums of 64-float segments: out[seg] = sum(Y[seg*64 .. seg*64+63])
// Raw segment layout: seg = l*512 + b*8 + h   (from torch raw reshape)
// ---------------------------------------------------------------------------
__global__ void __launch_bounds__(256) k_rowsum64(const float* __restrict__ Y,
                                                  float* __restrict__ out)
{
    int seg  = blockIdx.x * 8 + (threadIdx.x >> 5);
    int lane = threadIdx.x & 31;
    const float* p = Y + (size_t)seg*64;
    float v = p[lane] + p[lane + 32];
#pragma unroll
    for (int o = 16; o; o >>= 1) v += __shfl_down_sync(0xffffffffu, v, o);
    if (lane == 0) out[seg] = v;
}

// ---------------------------------------------------------------------------
// Attention prep (per (l,h)): A1[kk]=sum_m ks[m]*a[kk,m];
// A2[kk]=sum_m (ks[m]-1e9*m)*a[kk,m]; S1=sum_kk A1.
// Skew closed form: p = 127*kk + 63 + m; i' = p>>7; c = p&127;
//   a[kk,m] = (c<64) ? rel[l,h,i',c] : 0
// ---------------------------------------------------------------------------
__global__ void __launch_bounds__(256) k_attn_prep(const float* __restrict__ rel,
                                                   const float* __restrict__ ks,
                                                   float* __restrict__ A2,
                                                   float* __restrict__ S1)
{
    __shared__ float tile[4096];
    __shared__ float kss[64];
    __shared__ float a1p[64][4];
    __shared__ float a2p[64][4];

    int lh = blockIdx.x;            // l*8 + h
    int l  = lh >> 3, h = lh & 7;
    int t  = threadIdx.x;

    const float* rp = rel + (size_t)lh*4096;
    for (int i = t; i < 4096; i += 256) tile[i] = rp[i];
    if (t < 64) kss[t] = ks[(l << 9) + (t << 3) + h];
    __syncthreads();

    int kk = t & 63, q = t >> 6;
    float a1 = 0.f, a2 = 0.f;
    int base = 127*kk + 63;
    for (int m = q*16; m < q*16 + 16; m++) {
        int p = base + m;
        int c = p & 127;
        if (c < 64) {
            float a = tile[((p >> 7) << 6) + c];
            float km = kss[m];
            a1 = fmaf(km, a, a1);
            a2 = fmaf(km - 1e9f*(float)m, a, a2);
        }
    }
    a1p[kk][q] = a1;
    a2p[kk][q] = a2;
    __syncthreads();

    if (t < 64) {
        float A1v = a1p[t][0] + a1p[t][1] + a1p[t][2] + a1p[t][3];
        float A2v = a2p[t][0] + a2p[t][1] + a2p[t][2] + a2p[t][3];
        A2[lh*64 + t] = A2v;
        a1p[t][0] = A1v;
    }
    __syncthreads();
    if (t == 0) {
        float s = 0.f;
        for (int i = 0; i < 64; i++) s += a1p[i][0];
        S1[lh] = s;
    }
}

// ---------------------------------------------------------------------------
// Attention softmax + PV (per (l,h)). scores[j,kk] = (sc^2*S1*qs[j])*A2[kk]
// (+ -1e9 for kk>j if causal). o[j,n] = sum_kk p[j,kk]*v[kk,n].
// Output written at raw-reshape target: out[l*32768 + h*4096 + j*64 + n].
// ---------------------------------------------------------------------------
__global__ void __launch_bounds__(256) k_attn_out(const float* __restrict__ Yv,
                                                  const float* __restrict__ qs,
                                                  const float* __restrict__ A2,
                                                  const float* __restrict__ S1,
                                                  float* __restrict__ out,
                                                  int causal)
{
    __shared__ float vtile[64][64];
    __shared__ float a2s[64];
    __shared__ float qss[64];
    __shared__ float ps[8][64];

    int lh = blockIdx.x;
    int l = lh >> 3, h = lh & 7;
    int t = threadIdx.x, w = t >> 5, lane = t & 31;

    const float* vbase = Yv + (size_t)l*32768 + h*64;
    for (int i = t; i < 4096; i += 256) {
        int kk = i >> 6, n = i & 63;
        vtile[kk][n] = vbase[(size_t)kk*512 + n];
    }
    if (t < 64) {
        a2s[t] = A2[lh*64 + t];
        qss[t] = qs[(l << 9) + (t << 3) + h];
    }
    __syncthreads();

    float cb = SC2 * S1[lh];
    size_t obase = (size_t)l*32768 + (size_t)h*4096;

    for (int j = w; j < 64; j += 8) {
        float cj = cb * qss[j];
        float s0 = cj * a2s[lane];
        float s1 = cj * a2s[lane + 32];
        if (causal) {
            if (lane > j)      s0 += -1e9f;
            if (lane + 32 > j) s1 += -1e9f;
        }
        float mx = fmaxf(s0, s1);
#pragma unroll
        for (int o = 16; o; o >>= 1) mx = fmaxf(mx, __shfl_xor_sync(0xffffffffu, mx, o));
        float e0 = expf(s0 - mx), e1 = expf(s1 - mx);
        float sum = e0 + e1;
#pragma unroll
        for (int o = 16; o; o >>= 1) sum += __shfl_xor_sync(0xffffffffu, sum, o);
        float inv = 1.f / sum;
        ps[w][lane]      = e0 * inv;
        ps[w][lane + 32] = e1 * inv;
        __syncwarp();

        float acc0 = 0.f, acc1 = 0.f;
#pragma unroll 8
        for (int kk = 0; kk < 64; kk++) {
            float p = ps[w][kk];
            acc0 = fmaf(p, vtile[kk][lane],      acc0);
            acc1 = fmaf(p, vtile[kk][lane + 32], acc1);
        }
        out[obase + j*64 + lane]      = acc0;
        out[obase + j*64 + lane + 32] = acc1;
        __syncwarp();
    }
}

// ---------------------------------------------------------------------------
// out = LayerNorm(X + Y) over 512 (no affine, eps=1e-5, biased var)
// ---------------------------------------------------------------------------
__global__ void __launch_bounds__(256) k_addln(const float* __restrict__ X,
                                               const float* __restrict__ Y,
                                               float* __restrict__ out)
{
    __shared__ float rs[8], rq[8];
    int r = blockIdx.x, t = threadIdx.x;
    const float* xr = X + (size_t)r*512;
    const float* yr = Y + (size_t)r*512;
    float v0 = xr[t]       + yr[t];
    float v1 = xr[t + 256] + yr[t + 256];
    float sum = v0 + v1;
    float sq  = v0*v0 + v1*v1;
    int lane = t & 31, w = t >> 5;
#pragma unroll
    for (int o = 16; o; o >>= 1) {
        sum += __shfl_xor_sync(0xffffffffu, sum, o);
        sq  += __shfl_xor_sync(0xffffffffu, sq,  o);
    }
    if (lane == 0) { rs[w] = sum; rq[w] = sq; }
    __syncthreads();
    float ts = 0.f, tq = 0.f;
#pragma unroll
    for (int i = 0; i < 8; i++) { ts += rs[i]; tq += rq[i]; }
    float mu  = ts * (1.f/512.f);
    float var = tq * (1.f/512.f) - mu*mu;
    float inv = 1.f / sqrtf(var + 1e-5f);
    out[(size_t)r*512 + t]       = (v0 - mu) * inv;
    out[(size_t)r*512 + t + 256] = (v1 - mu) * inv;
}

// ---------------------------------------------------------------------------
// Final: out[r,:] = softmax(x[r,:] @ W_out + B_out) over 64
// ---------------------------------------------------------------------------
__global__ void __launch_bounds__(64) k_outproj(const float* __restrict__ X,
                                                const float* __restrict__ W,
                                                const float* __restrict__ b,
                                                float* __restrict__ out)
{
    __shared__ float xs[512];
    __shared__ float lg[64];
    int r = blockIdx.x, t = threadIdx.x;
    const float* xr = X + (size_t)r*512;
    for (int i = t; i < 512; i += 64) xs[i] = xr[i];
    __syncthreads();
    float acc = b[t];
#pragma unroll 8
    for (int c = 0; c < 512; c++) acc = fmaf(xs[c], W[c*64 + t], acc);
    lg[t] = acc;
    __syncthreads();
    float mx = -3.4e38f;
    for (int i = 0; i < 64; i++) mx = fmaxf(mx, lg[i]);
    __syncthreads();
    float e = expf(acc - mx);
    lg[t] = e;
    __syncthreads();
    float s = 0.f;
    for (int i = 0; i < 64; i++) s += lg[i];
    out[(size_t)r*64 + t] = e / s;
}

// ---------------------------------------------------------------------------
// Host orchestration
// ---------------------------------------------------------------------------
static void run_attn(const float* xq, const float* xk, const float* xv,
                     const float* wq, const float* wk, const float* wv,
                     const float* rel, int causal,
                     float* Q, float* K, float* V,
                     float* QS, float* KS, float* A2, float* S1, float* OUT)
{
    dim3 gqkv(4, 128);
    k_gemm<<<gqkv, 256>>>(xq, wq, nullptr, Q, NROW, 512, 512, 0);
    k_gemm<<<gqkv, 256>>>(xk, wk, nullptr, K, NROW, 512, 512, 0);
    k_gemm<<<gqkv, 256>>>(xv, wv, nullptr, V, NROW, 512, 512, 0);
    k_rowsum64<<<NROW, 256>>>(Q, QS);
    k_rowsum64<<<NROW, 256>>>(K, KS);
    k_attn_prep<<<LLEN*HN, 256>>>(rel, KS, A2, S1);
    k_attn_out<<<LLEN*HN, 256>>>(V, QS, A2, S1, OUT, causal);
}

extern "C" void kernel_launch(void* const* d_in, const int* in_sizes, int n_in,
                              void* d_out, int out_size)
{
    const float* X_en   = (const float*)d_in[0];
    const float* X_de   = (const float*)d_in[1];
    const float* W_in   = (const float*)d_in[2];
    const float* B_in   = (const float*)d_in[3];
    const float* enc_wq = (const float*)d_in[4];
    const float* enc_wk = (const float*)d_in[5];
    const float* enc_wv = (const float*)d_in[6];
    const float* enc_rel= (const float*)d_in[7];
    const float* enc_w1 = (const float*)d_in[8];
    const float* enc_b1 = (const float*)d_in[9];
    const float* enc_w2 = (const float*)d_in[10];
    const float* enc_b2 = (const float*)d_in[11];
    const float* dec_wq1= (const float*)d_in[12];
    const float* dec_wk1= (const float*)d_in[13];
    const float* dec_wv1= (const float*)d_in[14];
    const float* dec_rel1=(const float*)d_in[15];
    const float* dec_wq2= (const float*)d_in[16];
    const float* dec_wk2= (const float*)d_in[17];
    const float* dec_wv2= (const float*)d_in[18];
    const float* dec_rel2=(const float*)d_in[19];
    const float* dec_w1 = (const float*)d_in[20];
    const float* dec_b1 = (const float*)d_in[21];
    const float* dec_w2 = (const float*)d_in[22];
    const float* dec_b2 = (const float*)d_in[23];
    const float* W_out  = (const float*)d_in[24];
    const float* B_out  = (const float*)d_in[25];
    float* OUT = (float*)d_out;

    float *xen,*xde,*Q,*K,*V,*ATT,*bufA,*bufB,*enc,*ffh,*ffo,*qs,*ks,*a2,*s1;
    cudaGetSymbolAddress((void**)&xen,  g_xen);
    cudaGetSymbolAddress((void**)&xde,  g_xde);
    cudaGetSymbolAddress((void**)&Q,    g_q);
    cudaGetSymbolAddress((void**)&K,    g_k);
    cudaGetSymbolAddress((void**)&V,    g_v);
    cudaGetSymbolAddress((void**)&ATT,  g_attn);
    cudaGetSymbolAddress((void**)&bufA, g_bufA);
    cudaGetSymbolAddress((void**)&bufB, g_bufB);
    cudaGetSymbolAddress((void**)&enc,  g_enc);
    cudaGetSymbolAddress((void**)&ffh,  g_ffh);
    cudaGetSymbolAddress((void**)&ffo,  g_ffo);
    cudaGetSymbolAddress((void**)&qs,   g_qs);
    cudaGetSymbolAddress((void**)&ks,   g_ks);
    cudaGetSymbolAddress((void**)&a2,   g_a2);
    cudaGetSymbolAddress((void**)&s1,   g_s1);

    // Embeddings
    k_embed<<<NROW, 128>>>(X_en, W_in, B_in, xen);
    k_embed<<<NROW, 128>>>(X_de, W_in, B_in, xde);

    // ---------------- Encoder ----------------
    run_attn(xen, xen, xen, enc_wq, enc_wk, enc_wv, enc_rel, 0,
             Q, K, V, qs, ks, a2, s1, ATT);
    k_addln<<<NROW, 256>>>(xen, ATT, bufA);                          // o1
    k_gemm<<<dim3(16,128), 256>>>(bufA, enc_w1, enc_b1, ffh, NROW, DFF, 512, 3);
    k_gemm<<<dim3(4,128),  256>>>(ffh,  enc_w2, enc_b2, ffo, NROW, 512, DFF, 1);
    k_addln<<<NROW, 256>>>(bufA, ffo, enc);                          // enc_out

    // ---------------- Decoder self-attn (causal) ----------------
    run_attn(xde, xde, xde, dec_wq1, dec_wk1, dec_wv1, dec_rel1, 1,
             Q, K, V, qs, ks, a2, s1, ATT);
    k_addln<<<NROW, 256>>>(xde, ATT, bufA);                          // m

    // ---------------- Decoder cross-attn ----------------
    run_attn(bufA, enc, enc, dec_wq2, dec_wk2, dec_wv2, dec_rel2, 0,
             Q, K, V, qs, ks, a2, s1, ATT);
    k_addln<<<NROW, 256>>>(ATT, bufA, bufB);                         // c

    // ---------------- Decoder FFN ----------------
    k_gemm<<<dim3(16,128), 256>>>(bufB, dec_w1, dec_b1, ffh, NROW, DFF, 512, 3);
    k_gemm<<<dim3(4,128),  256>>>(ffh,  dec_w2, dec_b2, ffo, NROW, 512, DFF, 1);
    k_addln<<<NROW, 256>>>(bufB, ffo, bufA);

    // ---------------- Output projection + softmax ----------------
    k_outproj<<<NROW, 64>>>(bufA, W_out, B_out, OUT);

    (void)in_sizes; (void)n_in; (void)out_size;
}

// round 2
// speedup vs baseline: 1.1263x; 1.1263x over previous
#include <cuda_runtime.h>
#include <math.h>

// ---------------------------------------------------------------------------
// Problem constants
// ---------------------------------------------------------------------------
#define NROW  16384          // B*L = 64*256
#define DMODEL 512
#define DFF   2048
#define LLEN  256
#define BB    64
#define HN    8
#define NSEG  (LLEN*HN*BB)
#define SC2   (1.0f/64.0f)

// ---------------------------------------------------------------------------
// Scratch
// ---------------------------------------------------------------------------
__device__ float g_xen [NROW*DMODEL];
__device__ float g_xde [NROW*DMODEL];
__device__ float g_q   [NROW*DMODEL];
__device__ float g_k   [NROW*DMODEL];
__device__ float g_v   [NROW*DMODEL];
__device__ float g_attn[NROW*DMODEL];
__device__ float g_bufA[NROW*DMODEL];
__device__ float g_bufB[NROW*DMODEL];
__device__ float g_enc [NROW*DMODEL];
__device__ float g_ffh [NROW*DFF];
__device__ float g_ffo [NROW*DMODEL];
__device__ float g_qs  [NSEG];
__device__ float g_ks  [NSEG];
__device__ float g_a2  [NSEG];
__device__ float g_s1  [LLEN*HN];

// ---------------------------------------------------------------------------
// Packed f32x2 helpers (FFMA2 path — only reachable via PTX)
// ---------------------------------------------------------------------------
__device__ __forceinline__ unsigned long long pk2(float lo, float hi) {
    unsigned long long r;
    asm("mov.b64 %0, {%1,%2};" : "=l"(r) : "f"(lo), "f"(hi));
    return r;
}
__device__ __forceinline__ void fma2(unsigned long long& d,
                                     unsigned long long a,
                                     unsigned long long b) {
    asm("fma.rn.f32x2 %0, %1, %2, %0;" : "+l"(d) : "l"(a), "l"(b));
}
__device__ __forceinline__ float2 upk2(unsigned long long v) {
    float lo, hi;
    asm("mov.b64 {%0,%1}, %2;" : "=f"(lo), "=f"(hi) : "l"(v));
    return make_float2(lo, hi);
}

// ---------------------------------------------------------------------------
// Embed: x[r, :] = Xraw[r*64 .. r*64+63] @ W_in + B_in
// ---------------------------------------------------------------------------
__global__ void __launch_bounds__(128) k_embed(const float* __restrict__ X,
                                               const float* __restrict__ W,
                                               const float* __restrict__ b,
                                               float* __restrict__ out)
{
    __shared__ float xs[64];
    int r = blockIdx.x;
    int t = threadIdx.x;
    if (t < 64) xs[t] = X[(size_t)r*64 + t];
    __syncthreads();
#pragma unroll
    for (int i = 0; i < 4; i++) {
        int d = t + i*128;
        float acc = b[d];
#pragma unroll 16
        for (int c = 0; c < 64; c++) acc = fmaf(xs[c], W[c*512 + d], acc);
        out[(size_t)r*512 + d] = acc;
    }
}

// ---------------------------------------------------------------------------
// SGEMM (FFMA2): C[M,N] = A[M,K] @ B[K,N]  (+bias, +relu via flags)
// BM=BN=128, BK=16, 256 threads, 8x8 per thread via 32 packed f32x2 FMAs.
// Double-buffered smem, ONE __syncthreads per k-tile.
// flags: bit0 = add bias, bit1 = relu
// ---------------------------------------------------------------------------
#define BM 128
#define BN 128
#define BK 16
#define APAD 4   // 128+4=132 floats; 132*4=528 bytes, multiple of 16 (LDS.128 ok)

__global__ void __launch_bounds__(256, 2) k_gemm(const float* __restrict__ A,
                                                 const float* __restrict__ B,
                                                 const float* __restrict__ bias,
                                                 float* __restrict__ C,
                                                 int M, int N, int K, int flags)
{
    __shared__ __align__(16) float As[2][BK][BM + APAD];  // transposed A
    __shared__ __align__(16) float Bs[2][BK][BN];

    int tid = threadIdx.x;
    int bm = blockIdx.y * BM;
    int bn = blockIdx.x * BN;
    int ty = tid >> 4;          // 0..15
    int tx = tid & 15;          // 0..15

    // Load mappings
    int arow = tid >> 2;        // 0..63
    int acol = (tid & 3) * 4;   // 0,4,8,12
    int brow = tid >> 4;        // 0..15
    int bcol = (tid & 15) * 8;  // 0..120

    const float* Ap = A + (size_t)(bm + arow)*K + acol;
    const float* Bp = B + (size_t)brow*N + bn + bcol;

    int T = K / BK;

    // Prologue: load tile 0 into regs
    float4 a0 = *(const float4*)(Ap);
    float4 a1 = *(const float4*)(Ap + (size_t)64*K);
    float4 b0 = *(const float4*)(Bp);
    float4 b1 = *(const float4*)(Bp + 4);

    unsigned long long acc2[8][4];
#pragma unroll
    for (int i = 0; i < 8; i++)
#pragma unroll
        for (int j = 0; j < 4; j++) acc2[i][j] = 0ULL;

    for (int kt = 0; kt < T; ++kt) {
        int s = kt & 1;
        // store staged tile into buffer s
        As[s][acol+0][arow] = a0.x;
        As[s][acol+1][arow] = a0.y;
        As[s][acol+2][arow] = a0.z;
        As[s][acol+3][arow] = a0.w;
        As[s][acol+0][arow+64] = a1.x;
        As[s][acol+1][arow+64] = a1.y;
        As[s][acol+2][arow+64] = a1.z;
        As[s][acol+3][arow+64] = a1.w;
        *(float4*)&Bs[s][brow][bcol]     = b0;
        *(float4*)&Bs[s][brow][bcol + 4] = b1;
        __syncthreads();

        // prefetch next tile
        if (kt + 1 < T) {
            const float* Ap2 = Ap + (kt + 1) * BK;
            a0 = *(const float4*)(Ap2);
            a1 = *(const float4*)(Ap2 + (size_t)64*K);
            const float* Bp2 = Bp + (size_t)(kt + 1) * BK * N;
            b0 = *(const float4*)(Bp2);
            b1 = *(const float4*)(Bp2 + 4);
        }

        // compute on buffer s
#pragma unroll
        for (int k = 0; k < BK; k++) {
            float4 av0 = *(const float4*)&As[s][k][ty*8];
            float4 av1 = *(const float4*)&As[s][k][ty*8 + 4];
            ulonglong2 bp0 = *(const ulonglong2*)&Bs[s][k][tx*8];
            ulonglong2 bp1 = *(const ulonglong2*)&Bs[s][k][tx*8 + 4];

            unsigned long long ad[8];
            ad[0] = pk2(av0.x, av0.x);
            ad[1] = pk2(av0.y, av0.y);
            ad[2] = pk2(av0.z, av0.z);
            ad[3] = pk2(av0.w, av0.w);
            ad[4] = pk2(av1.x, av1.x);
            ad[5] = pk2(av1.y, av1.y);
            ad[6] = pk2(av1.z, av1.z);
            ad[7] = pk2(av1.w, av1.w);

#pragma unroll
            for (int i = 0; i < 8; i++) {
                fma2(acc2[i][0], ad[i], bp0.x);
                fma2(acc2[i][1], ad[i], bp0.y);
                fma2(acc2[i][2], ad[i], bp1.x);
                fma2(acc2[i][3], ad[i], bp1.y);
            }
        }
        __syncthreads();
    }

    // Epilogue
    float bias4[8];
    if (flags & 1) {
#pragma unroll
        for (int j = 0; j < 8; j++) bias4[j] = bias[bn + tx*8 + j];
    }
#pragma unroll
    for (int i = 0; i < 8; i++) {
        size_t row = (size_t)(bm + ty*8 + i);
        float* cp = C + row*N + bn + tx*8;
        float out[8];
#pragma unroll
        for (int jj = 0; jj < 4; jj++) {
            float2 f = upk2(acc2[i][jj]);
            out[2*jj]   = f.x;
            out[2*jj+1] = f.y;
        }
        if (flags & 1) {
#pragma unroll
            for (int j = 0; j < 8; j++) out[j] += bias4[j];
        }
        if (flags & 2) {
#pragma unroll
            for (int j = 0; j < 8; j++) out[j] = fmaxf(out[j], 0.f);
        }
        *(float4*)(cp)     = make_float4(out[0], out[1], out[2], out[3]);
        *(float4*)(cp + 4) = make_float4(out[4], out[5], out[6], out[7]);
    }
}

// ---------------------------------------------------------------------------
// Row-sums of 64-float segments
// ---------------------------------------------------------------------------
__global__ void __launch_bounds__(256) k_rowsum64(const float* __restrict__ Y,
                                                  float* __restrict__ out)
{
    int seg  = blockIdx.x * 8 + (threadIdx.x >> 5);
    int lane = threadIdx.x & 31;
    const float* p = Y + (size_t)seg*64;
    float v = p[lane] + p[lane + 32];
#pragma unroll
    for (int o = 16; o; o >>= 1) v += __shfl_down_sync(0xffffffffu, v, o);
    if (lane == 0) out[seg] = v;
}

// ---------------------------------------------------------------------------
// Attention prep (per (l,h))
// ---------------------------------------------------------------------------
__global__ void __launch_bounds__(256) k_attn_prep(const float* __restrict__ rel,
                                                   const float* __restrict__ ks,
                                                   float* __restrict__ A2,
                                                   float* __restrict__ S1)
{
    __shared__ float tile[4096];
    __shared__ float kss[64];
    __shared__ float a1p[64][4];
    __shared__ float a2p[64][4];

    int lh = blockIdx.x;
    int l  = lh >> 3, h = lh & 7;
    int t  = threadIdx.x;

    const float* rp = rel + (size_t)lh*4096;
    for (int i = t; i < 4096; i += 256) tile[i] = rp[i];
    if (t < 64) kss[t] = ks[(l << 9) + (t << 3) + h];
    __syncthreads();

    int kk = t & 63, q = t >> 6;
    float a1 = 0.f, a2 = 0.f;
    int base = 127*kk + 63;
    for (int m = q*16; m < q*16 + 16; m++) {
        int p = base + m;
        int c = p & 127;
        if (c < 64) {
            float a = tile[((p >> 7) << 6) + c];
            float km = kss[m];
            a1 = fmaf(km, a, a1);
            a2 = fmaf(km - 1e9f*(float)m, a, a2);
        }
    }
    a1p[kk][q] = a1;
    a2p[kk][q] = a2;
    __syncthreads();

    if (t < 64) {
        float A1v = a1p[t][0] + a1p[t][1] + a1p[t][2] + a1p[t][3];
        float A2v = a2p[t][0] + a2p[t][1] + a2p[t][2] + a2p[t][3];
        A2[lh*64 + t] = A2v;
        a1p[t][0] = A1v;
    }
    __syncthreads();
    if (t == 0) {
        float s = 0.f;
        for (int i = 0; i < 64; i++) s += a1p[i][0];
        S1[lh] = s;
    }
}

// ---------------------------------------------------------------------------
// Attention softmax + PV (per (l,h))
// ---------------------------------------------------------------------------
__global__ void __launch_bounds__(256) k_attn_out(const float* __restrict__ Yv,
                                                  const float* __restrict__ qs,
                                                  const float* __restrict__ A2,
                                                  const float* __restrict__ S1,
                                                  float* __restrict__ out,
                                                  int causal)
{
    __shared__ float vtile[64][64];
    __shared__ float a2s[64];
    __shared__ float qss[64];
    __shared__ float ps[8][64];

    int lh = blockIdx.x;
    int l = lh >> 3, h = lh & 7;
    int t = threadIdx.x, w = t >> 5, lane = t & 31;

    const float* vbase = Yv + (size_t)l*32768 + h*64;
    for (int i = t; i < 4096; i += 256) {
        int kk = i >> 6, n = i & 63;
        vtile[kk][n] = vbase[(size_t)kk*512 + n];
    }
    if (t < 64) {
        a2s[t] = A2[lh*64 + t];
        qss[t] = qs[(l << 9) + (t << 3) + h];
    }
    __syncthreads();

    float cb = SC2 * S1[lh];
    size_t obase = (size_t)l*32768 + (size_t)h*4096;

    for (int j = w; j < 64; j += 8) {
        float cj = cb * qss[j];
        float s0 = cj * a2s[lane];
        float s1 = cj * a2s[lane + 32];
        if (causal) {
            if (lane > j)      s0 += -1e9f;
            if (lane + 32 > j) s1 += -1e9f;
        }
        float mx = fmaxf(s0, s1);
#pragma unroll
        for (int o = 16; o; o >>= 1) mx = fmaxf(mx, __shfl_xor_sync(0xffffffffu, mx, o));
        float e0 = expf(s0 - mx), e1 = expf(s1 - mx);
        float sum = e0 + e1;
#pragma unroll
        for (int o = 16; o; o >>= 1) sum += __shfl_xor_sync(0xffffffffu, sum, o);
        float inv = 1.f / sum;
        ps[w][lane]      = e0 * inv;
        ps[w][lane + 32] = e1 * inv;
        __syncwarp();

        float acc0 = 0.f, acc1 = 0.f;
#pragma unroll 8
        for (int kk = 0; kk < 64; kk++) {
            float p = ps[w][kk];
            acc0 = fmaf(p, vtile[kk][lane],      acc0);
            acc1 = fmaf(p, vtile[kk][lane + 32], acc1);
        }
        out[obase + j*64 + lane]      = acc0;
        out[obase + j*64 + lane + 32] = acc1;
        __syncwarp();
    }
}

// ---------------------------------------------------------------------------
// out = LayerNorm(X + Y)
// ---------------------------------------------------------------------------
__global__ void __launch_bounds__(256) k_addln(const float* __restrict__ X,
                                               const float* __restrict__ Y,
                                               float* __restrict__ out)
{
    __shared__ float rs[8], rq[8];
    int r = blockIdx.x, t = threadIdx.x;
    const float* xr = X + (size_t)r*512;
    const float* yr = Y + (size_t)r*512;
    float v0 = xr[t]       + yr[t];
    float v1 = xr[t + 256] + yr[t + 256];
    float sum = v0 + v1;
    float sq  = v0*v0 + v1*v1;
    int lane = t & 31, w = t >> 5;
#pragma unroll
    for (int o = 16; o; o >>= 1) {
        sum += __shfl_xor_sync(0xffffffffu, sum, o);
        sq  += __shfl_xor_sync(0xffffffffu, sq,  o);
    }
    if (lane == 0) { rs[w] = sum; rq[w] = sq; }
    __syncthreads();
    float ts = 0.f, tq = 0.f;
#pragma unroll
    for (int i = 0; i < 8; i++) { ts += rs[i]; tq += rq[i]; }
    float mu  = ts * (1.f/512.f);
    float var = tq * (1.f/512.f) - mu*mu;
    float inv = 1.f / sqrtf(var + 1e-5f);
    out[(size_t)r*512 + t]       = (v0 - mu) * inv;
    out[(size_t)r*512 + t + 256] = (v1 - mu) * inv;
}

// ---------------------------------------------------------------------------
// Final: out[r,:] = softmax(x[r,:] @ W_out + B_out) over 64
// ---------------------------------------------------------------------------
__global__ void __launch_bounds__(64) k_outproj(const float* __restrict__ X,
                                                const float* __restrict__ W,
                                                const float* __restrict__ b,
                                                float* __restrict__ out)
{
    __shared__ float xs[512];
    __shared__ float lg[64];
    int r = blockIdx.x, t = threadIdx.x;
    const float* xr = X + (size_t)r*512;
    for (int i = t; i < 512; i += 64) xs[i] = xr[i];
    __syncthreads();
    float acc = b[t];
#pragma unroll 8
    for (int c = 0; c < 512; c++) acc = fmaf(xs[c], W[c*64 + t], acc);
    lg[t] = acc;
    __syncthreads();
    float mx = -3.4e38f;
    for (int i = 0; i < 64; i++) mx = fmaxf(mx, lg[i]);
    __syncthreads();
    float e = expf(acc - mx);
    lg[t] = e;
    __syncthreads();
    float s = 0.f;
    for (int i = 0; i < 64; i++) s += lg[i];
    out[(size_t)r*64 + t] = e / s;
}

// ---------------------------------------------------------------------------
// Host orchestration
// ---------------------------------------------------------------------------
static void run_attn(const float* xq, const float* xk, const float* xv,
                     const float* wq, const float* wk, const float* wv,
                     const float* rel, int causal,
                     float* Q, float* K, float* V,
                     float* QS, float* KS, float* A2, float* S1, float* OUT)
{
    dim3 gqkv(4, 128);
    k_gemm<<<gqkv, 256>>>(xq, wq, nullptr, Q, NROW, 512, 512, 0);
    k_gemm<<<gqkv, 256>>>(xk, wk, nullptr, K, NROW, 512, 512, 0);
    k_gemm<<<gqkv, 256>>>(xv, wv, nullptr, V, NROW, 512, 512, 0);
    k_rowsum64<<<NROW, 256>>>(Q, QS);
    k_rowsum64<<<NROW, 256>>>(K, KS);
    k_attn_prep<<<LLEN*HN, 256>>>(rel, KS, A2, S1);
    k_attn_out<<<LLEN*HN, 256>>>(V, QS, A2, S1, OUT, causal);
}

extern "C" void kernel_launch(void* const* d_in, const int* in_sizes, int n_in,
                              void* d_out, int out_size)
{
    const float* X_en   = (const float*)d_in[0];
    const float* X_de   = (const float*)d_in[1];
    const float* W_in   = (const float*)d_in[2];
    const float* B_in   = (const float*)d_in[3];
    const float* enc_wq = (const float*)d_in[4];
    const float* enc_wk = (const float*)d_in[5];
    const float* enc_wv = (const float*)d_in[6];
    const float* enc_rel= (const float*)d_in[7];
    const float* enc_w1 = (const float*)d_in[8];
    const float* enc_b1 = (const float*)d_in[9];
    const float* enc_w2 = (const float*)d_in[10];
    const float* enc_b2 = (const float*)d_in[11];
    const float* dec_wq1= (const float*)d_in[12];
    const float* dec_wk1= (const float*)d_in[13];
    const float* dec_wv1= (const float*)d_in[14];
    const float* dec_rel1=(const float*)d_in[15];
    const float* dec_wq2= (const float*)d_in[16];
    const float* dec_wk2= (const float*)d_in[17];
    const float* dec_wv2= (const float*)d_in[18];
    const float* dec_rel2=(const float*)d_in[19];
    const float* dec_w1 = (const float*)d_in[20];
    const float* dec_b1 = (const float*)d_in[21];
    const float* dec_w2 = (const float*)d_in[22];
    const float* dec_b2 = (const float*)d_in[23];
    const float* W_out  = (const float*)d_in[24];
    const float* B_out  = (const float*)d_in[25];
    float* OUT = (float*)d_out;

    float *xen,*xde,*Q,*K,*V,*ATT,*bufA,*bufB,*enc,*ffh,*ffo,*qs,*ks,*a2,*s1;
    cudaGetSymbolAddress((void**)&xen,  g_xen);
    cudaGetSymbolAddress((void**)&xde,  g_xde);
    cudaGetSymbolAddress((void**)&Q,    g_q);
    cudaGetSymbolAddress((void**)&K,    g_k);
    cudaGetSymbolAddress((void**)&V,    g_v);
    cudaGetSymbolAddress((void**)&ATT,  g_attn);
    cudaGetSymbolAddress((void**)&bufA, g_bufA);
    cudaGetSymbolAddress((void**)&bufB, g_bufB);
    cudaGetSymbolAddress((void**)&enc,  g_enc);
    cudaGetSymbolAddress((void**)&ffh,  g_ffh);
    cudaGetSymbolAddress((void**)&ffo,  g_ffo);
    cudaGetSymbolAddress((void**)&qs,   g_qs);
    cudaGetSymbolAddress((void**)&ks,   g_ks);
    cudaGetSymbolAddress((void**)&a2,   g_a2);
    cudaGetSymbolAddress((void**)&s1,   g_s1);

    // Embeddings
    k_embed<<<NROW, 128>>>(X_en, W_in, B_in, xen);
    k_embed<<<NROW, 128>>>(X_de, W_in, B_in, xde);

    // ---------------- Encoder ----------------
    run_attn(xen, xen, xen, enc_wq, enc_wk, enc_wv, enc_rel, 0,
             Q, K, V, qs, ks, a2, s1, ATT);
    k_addln<<<NROW, 256>>>(xen, ATT, bufA);                          // o1
    k_gemm<<<dim3(16,128), 256>>>(bufA, enc_w1, enc_b1, ffh, NROW, DFF, 512, 3);
    k_gemm<<<dim3(4,128),  256>>>(ffh,  enc_w2, enc_b2, ffo, NROW, 512, DFF, 1);
    k_addln<<<NROW, 256>>>(bufA, ffo, enc);                          // enc_out

    // ---------------- Decoder self-attn (causal) ----------------
    run_attn(xde, xde, xde, dec_wq1, dec_wk1, dec_wv1, dec_rel1, 1,
             Q, K, V, qs, ks, a2, s1, ATT);
    k_addln<<<NROW, 256>>>(xde, ATT, bufA);                          // m

    // ---------------- Decoder cross-attn ----------------
    run_attn(bufA, enc, enc, dec_wq2, dec_wk2, dec_wv2, dec_rel2, 0,
             Q, K, V, qs, ks, a2, s1, ATT);
    k_addln<<<NROW, 256>>>(ATT, bufA, bufB);                         // c

    // ---------------- Decoder FFN ----------------
    k_gemm<<<dim3(16,128), 256>>>(bufB, dec_w1, dec_b1, ffh, NROW, DFF, 512, 3);
    k_gemm<<<dim3(4,128),  256>>>(ffh,  dec_w2, dec_b2, ffo, NROW, 512, DFF, 1);
    k_addln<<<NROW, 256>>>(bufB, ffo, bufA);

    // ---------------- Output projection + softmax ----------------
    k_outproj<<<NROW, 64>>>(bufA, W_out, B_out, OUT);

    (void)in_sizes; (void)n_in; (void)out_size;
}

// round 3
// speedup vs baseline: 1.4662x; 1.3017x over previous
#include <cuda_runtime.h>
#include <math.h>

// ---------------------------------------------------------------------------
// Problem constants
// ---------------------------------------------------------------------------
#define NROW  16384          // B*L = 64*256 (rows r = l*64 + b)
#define DMODEL 512
#define DFF   2048
#define LLEN  256
#define BB    64
#define HN    8
#define NSEG  (NROW*8)       // segments of 64: seg = r*8 + g
#define SC2   (1.0f/64.0f)

// ---------------------------------------------------------------------------
// Scratch
// ---------------------------------------------------------------------------
__device__ float g_xen [NROW*DMODEL];
__device__ float g_xde [NROW*DMODEL];
__device__ float g_v   [NROW*DMODEL];
__device__ float g_attn[NROW*DMODEL];
__device__ float g_bufA[NROW*DMODEL];
__device__ float g_bufB[NROW*DMODEL];
__device__ float g_enc [NROW*DMODEL];
__device__ float g_ffh [NROW*DFF];
__device__ float g_ffo [NROW*DMODEL];
__device__ float g_qs  [NSEG];
__device__ float g_ks  [NSEG];
__device__ float g_a2  [LLEN*HN*64];
__device__ float g_s1  [LLEN*HN];
__device__ float g_wg  [6*8*512];     // 6 row-summed weights, [g][c] layout

// ---------------------------------------------------------------------------
// Packed f32x2 helpers
// ---------------------------------------------------------------------------
__device__ __forceinline__ unsigned long long pk2(float lo, float hi) {
    unsigned long long r;
    asm("mov.b64 %0, {%1,%2};" : "=l"(r) : "f"(lo), "f"(hi));
    return r;
}
__device__ __forceinline__ void fma2(unsigned long long& d,
                                     unsigned long long a,
                                     unsigned long long b) {
    asm("fma.rn.f32x2 %0, %1, %2, %0;" : "+l"(d) : "l"(a), "l"(b));
}
__device__ __forceinline__ float2 upk2(unsigned long long v) {
    float lo, hi;
    asm("mov.b64 {%0,%1}, %2;" : "=f"(lo), "=f"(hi) : "l"(v));
    return make_float2(lo, hi);
}

// ---------------------------------------------------------------------------
// Embed: x[r, :] = Xraw[r*64 .. r*64+63] @ W_in + B_in
// ---------------------------------------------------------------------------
__global__ void __launch_bounds__(128) k_embed(const float* __restrict__ X,
                                               const float* __restrict__ W,
                                               const float* __restrict__ b,
                                               float* __restrict__ out)
{
    __shared__ float xs[64];
    int r = blockIdx.x;
    int t = threadIdx.x;
    if (t < 64) xs[t] = X[(size_t)r*64 + t];
    __syncthreads();
#pragma unroll
    for (int i = 0; i < 4; i++) {
        int d = t + i*128;
        float acc = b[d];
#pragma unroll 16
        for (int c = 0; c < 64; c++) acc = fmaf(xs[c], W[c*512 + d], acc);
        out[(size_t)r*512 + d] = acc;
    }
}

// ---------------------------------------------------------------------------
// Weight group-sum: wgT[g][c] = sum_{d in [g*64,(g+1)*64)} w[c][d]
// ---------------------------------------------------------------------------
__global__ void __launch_bounds__(256) k_wsum(const float* __restrict__ w,
                                              float* __restrict__ wgT)
{
    int idx = blockIdx.x*256 + threadIdx.x;   // 0..4095
    int g = idx >> 9, c = idx & 511;
    const float* p = w + (size_t)c*512 + g*64;
    float s = 0.f;
#pragma unroll 16
    for (int j = 0; j < 64; j++) s += p[j];
    wgT[g*512 + c] = s;
}

// ---------------------------------------------------------------------------
// qs/ks: qs[r*8+g] = sum_c xq[r,c] * wgq[g][c]  (same for ks with xk/wgk)
// One warp per row; wg tables staged in smem.
// ---------------------------------------------------------------------------
__global__ void __launch_bounds__(256) k_qks(const float* __restrict__ xq,
                                             const float* __restrict__ xk,
                                             const float* __restrict__ wgq,
                                             const float* __restrict__ wgk,
                                             float* __restrict__ qs,
                                             float* __restrict__ ks)
{
    __shared__ float sq[8][512];
    __shared__ float sk[8][512];
    int t = threadIdx.x;
    for (int i = t; i < 4096; i += 256) {
        sq[i >> 9][i & 511] = wgq[i];
        sk[i >> 9][i & 511] = wgk[i];
    }
    __syncthreads();

    int w = t >> 5, lane = t & 31;
    int r = blockIdx.x*8 + w;
    const float* xqr = xq + (size_t)r*512;
    const float* xkr = xk + (size_t)r*512;

    float aq0=0,aq1=0,aq2=0,aq3=0,aq4=0,aq5=0,aq6=0,aq7=0;
    float ak0=0,ak1=0,ak2=0,ak3=0,ak4=0,ak5=0,ak6=0,ak7=0;
#pragma unroll 4
    for (int i = 0; i < 16; i++) {
        int c = lane + 32*i;
        float xv = xqr[c];
        float kv = xkr[c];
        aq0 = fmaf(xv, sq[0][c], aq0);  ak0 = fmaf(kv, sk[0][c], ak0);
        aq1 = fmaf(xv, sq[1][c], aq1);  ak1 = fmaf(kv, sk[1][c], ak1);
        aq2 = fmaf(xv, sq[2][c], aq2);  ak2 = fmaf(kv, sk[2][c], ak2);
        aq3 = fmaf(xv, sq[3][c], aq3);  ak3 = fmaf(kv, sk[3][c], ak3);
        aq4 = fmaf(xv, sq[4][c], aq4);  ak4 = fmaf(kv, sk[4][c], ak4);
        aq5 = fmaf(xv, sq[5][c], aq5);  ak5 = fmaf(kv, sk[5][c], ak5);
        aq6 = fmaf(xv, sq[6][c], aq6);  ak6 = fmaf(kv, sk[6][c], ak6);
        aq7 = fmaf(xv, sq[7][c], aq7);  ak7 = fmaf(kv, sk[7][c], ak7);
    }
#pragma unroll
    for (int o = 16; o; o >>= 1) {
        aq0 += __shfl_xor_sync(~0u, aq0, o);  ak0 += __shfl_xor_sync(~0u, ak0, o);
        aq1 += __shfl_xor_sync(~0u, aq1, o);  ak1 += __shfl_xor_sync(~0u, ak1, o);
        aq2 += __shfl_xor_sync(~0u, aq2, o);  ak2 += __shfl_xor_sync(~0u, ak2, o);
        aq3 += __shfl_xor_sync(~0u, aq3, o);  ak3 += __shfl_xor_sync(~0u, ak3, o);
        aq4 += __shfl_xor_sync(~0u, aq4, o);  ak4 += __shfl_xor_sync(~0u, ak4, o);
        aq5 += __shfl_xor_sync(~0u, aq5, o);  ak5 += __shfl_xor_sync(~0u, ak5, o);
        aq6 += __shfl_xor_sync(~0u, aq6, o);  ak6 += __shfl_xor_sync(~0u, ak6, o);
        aq7 += __shfl_xor_sync(~0u, aq7, o);  ak7 += __shfl_xor_sync(~0u, ak7, o);
    }
    if (lane == 0) {
        float* q = qs + r*8;
        q[0]=aq0; q[1]=aq1; q[2]=aq2; q[3]=aq3; q[4]=aq4; q[5]=aq5; q[6]=aq6; q[7]=aq7;
    } else if (lane == 1) {
        float* k = ks + r*8;
        k[0]=ak0; k[1]=ak1; k[2]=ak2; k[3]=ak3; k[4]=ak4; k[5]=ak5; k[6]=ak6; k[7]=ak7;
    }
}

// ---------------------------------------------------------------------------
// SGEMM (FFMA2, 16x8 tile): C[M,N] = A[M,K] @ B[K,N]  (+bias, +relu)
// BM=BN=128, BK=16, 128 threads, 16m x 8n per thread, pairs packed along m.
// flags: bit0 = add bias, bit1 = relu
// ---------------------------------------------------------------------------
#define BM 128
#define BN 128
#define BK 16

__global__ void __launch_bounds__(128) k_gemm(const float* __restrict__ A,
                                              const float* __restrict__ B,
                                              const float* __restrict__ bias,
                                              float* __restrict__ C,
                                              int M, int N, int K, int flags)
{
    __shared__ __align__(16) float As[2][BK][BM + 4];  // [k][m]
    __shared__ __align__(16) float Bs[2][BK][BN];

    int tid = threadIdx.x;
    int bm = blockIdx.y * BM;
    int bn = blockIdx.x * BN;
    int tm = tid >> 4;          // 0..7  -> m0 = tm*16
    int tx = tid & 15;          // 0..15 -> n0 = tx*8

    // global load mappings
    int ar = tid >> 2;          // 0..31 (rows ar + 32i)
    int ac = (tid & 3) * 4;     // k-col group
    int br = tid >> 3;          // 0..15
    int bc = (tid & 7) * 16;    // n-col group
    const float* Ap = A + (size_t)(bm + ar)*K + ac;
    const float* Bp = B + (size_t)br*N + bn + bc;

    int T = K / BK;

    float4 pa[4], pb[4];
#pragma unroll
    for (int i = 0; i < 4; i++) pa[i] = *(const float4*)(Ap + (size_t)(32*i)*K);
#pragma unroll
    for (int i = 0; i < 4; i++) pb[i] = *(const float4*)(Bp + 4*i);

    unsigned long long acc[8][8];   // [m-pair][n]
#pragma unroll
    for (int p = 0; p < 8; p++)
#pragma unroll
        for (int n = 0; n < 8; n++) acc[p][n] = 0ULL;

    for (int kt = 0; kt < T; ++kt) {
        int s = kt & 1;
#pragma unroll
        for (int i = 0; i < 4; i++) {
            As[s][ac+0][ar + 32*i] = pa[i].x;
            As[s][ac+1][ar + 32*i] = pa[i].y;
            As[s][ac+2][ar + 32*i] = pa[i].z;
            As[s][ac+3][ar + 32*i] = pa[i].w;
        }
#pragma unroll
        for (int i = 0; i < 4; i++) *(float4*)&Bs[s][br][bc + 4*i] = pb[i];
        __syncthreads();

        if (kt + 1 < T) {
            const float* Ap2 = Ap + (kt + 1)*BK;
            const float* Bp2 = Bp + (size_t)(kt + 1)*BK*N;
#pragma unroll
            for (int i = 0; i < 4; i++) pa[i] = *(const float4*)(Ap2 + (size_t)(32*i)*K);
#pragma unroll
            for (int i = 0; i < 4; i++) pb[i] = *(const float4*)(Bp2 + 4*i);
        }

#pragma unroll
        for (int k = 0; k < BK; k++) {
            ulonglong2 a01 = *(const ulonglong2*)&As[s][k][tm*16];
            ulonglong2 a23 = *(const ulonglong2*)&As[s][k][tm*16 + 4];
            ulonglong2 a45 = *(const ulonglong2*)&As[s][k][tm*16 + 8];
            ulonglong2 a67 = *(const ulonglong2*)&As[s][k][tm*16 + 12];
            unsigned long long am[8] = {a01.x, a01.y, a23.x, a23.y,
                                        a45.x, a45.y, a67.x, a67.y};
            float4 b0 = *(const float4*)&Bs[s][k][tx*8];
            float4 b1 = *(const float4*)&Bs[s][k][tx*8 + 4];
            unsigned long long bd[8];
            bd[0] = pk2(b0.x, b0.x); bd[1] = pk2(b0.y, b0.y);
            bd[2] = pk2(b0.z, b0.z); bd[3] = pk2(b0.w, b0.w);
            bd[4] = pk2(b1.x, b1.x); bd[5] = pk2(b1.y, b1.y);
            bd[6] = pk2(b1.z, b1.z); bd[7] = pk2(b1.w, b1.w);
#pragma unroll
            for (int p = 0; p < 8; p++) {
                fma2(acc[p][0], am[p], bd[0]);
                fma2(acc[p][1], am[p], bd[1]);
                fma2(acc[p][2], am[p], bd[2]);
                fma2(acc[p][3], am[p], bd[3]);
                fma2(acc[p][4], am[p], bd[4]);
                fma2(acc[p][5], am[p], bd[5]);
                fma2(acc[p][6], am[p], bd[6]);
                fma2(acc[p][7], am[p], bd[7]);
            }
        }
        __syncthreads();
    }

    // Epilogue
    float bv[8];
    if (flags & 1) {
#pragma unroll
        for (int j = 0; j < 8; j++) bv[j] = bias[bn + tx*8 + j];
    }
#pragma unroll
    for (int p = 0; p < 8; p++) {
        float lo[8], hi[8];
#pragma unroll
        for (int n = 0; n < 8; n++) {
            float2 f = upk2(acc[p][n]);
            lo[n] = f.x; hi[n] = f.y;
        }
        if (flags & 1) {
#pragma unroll
            for (int n = 0; n < 8; n++) { lo[n] += bv[n]; hi[n] += bv[n]; }
        }
        if (flags & 2) {
#pragma unroll
            for (int n = 0; n < 8; n++) { lo[n] = fmaxf(lo[n], 0.f); hi[n] = fmaxf(hi[n], 0.f); }
        }
        size_t row0 = (size_t)(bm + tm*16 + 2*p);
        float* c0 = C + row0*N + bn + tx*8;
        float* c1 = c0 + N;
        *(float4*)(c0)     = make_float4(lo[0], lo[1], lo[2], lo[3]);
        *(float4*)(c0 + 4) = make_float4(lo[4], lo[5], lo[6], lo[7]);
        *(float4*)(c1)     = make_float4(hi[0], hi[1], hi[2], hi[3]);
        *(float4*)(c1 + 4) = make_float4(hi[4], hi[5], hi[6], hi[7]);
    }
}

// ---------------------------------------------------------------------------
// Attention prep (per (l,h))
// ---------------------------------------------------------------------------
__global__ void __launch_bounds__(256) k_attn_prep(const float* __restrict__ rel,
                                                   const float* __restrict__ ks,
                                                   float* __restrict__ A2,
                                                   float* __restrict__ S1)
{
    __shared__ float tile[4096];
    __shared__ float kss[64];
    __shared__ float a1p[64][4];
    __shared__ float a2p[64][4];

    int lh = blockIdx.x;
    int l  = lh >> 3, h = lh & 7;
    int t  = threadIdx.x;

    const float* rp = rel + (size_t)lh*4096;
    for (int i = t; i < 4096; i += 256) tile[i] = rp[i];
    if (t < 64) kss[t] = ks[(l << 9) + (t << 3) + h];
    __syncthreads();

    int kk = t & 63, q = t >> 6;
    float a1 = 0.f, a2 = 0.f;
    int base = 127*kk + 63;
    for (int m = q*16; m < q*16 + 16; m++) {
        int p = base + m;
        int c = p & 127;
        if (c < 64) {
            float a = tile[((p >> 7) << 6) + c];
            float km = kss[m];
            a1 = fmaf(km, a, a1);
            a2 = fmaf(km - 1e9f*(float)m, a, a2);
        }
    }
    a1p[kk][q] = a1;
    a2p[kk][q] = a2;
    __syncthreads();

    if (t < 64) {
        float A1v = a1p[t][0] + a1p[t][1] + a1p[t][2] + a1p[t][3];
        float A2v = a2p[t][0] + a2p[t][1] + a2p[t][2] + a2p[t][3];
        A2[lh*64 + t] = A2v;
        a1p[t][0] = A1v;
    }
    __syncthreads();
    if (t == 0) {
        float s = 0.f;
        for (int i = 0; i < 64; i++) s += a1p[i][0];
        S1[lh] = s;
    }
}

// ---------------------------------------------------------------------------
// Attention softmax + PV (per (l,h))
// ---------------------------------------------------------------------------
__global__ void __launch_bounds__(256) k_attn_out(const float* __restrict__ Yv,
                                                  const float* __restrict__ qs,
                                                  const float* __restrict__ A2,
                                                  const float* __restrict__ S1,
                                                  float* __restrict__ out,
                                                  int causal)
{
    __shared__ float vtile[64][64];
    __shared__ float a2s[64];
    __shared__ float qss[64];
    __shared__ float ps[8][64];

    int lh = blockIdx.x;
    int l = lh >> 3, h = lh & 7;
    int t = threadIdx.x, w = t >> 5, lane = t & 31;

    const float* vbase = Yv + (size_t)l*32768 + h*64;
    for (int i = t; i < 4096; i += 256) {
        int kk = i >> 6, n = i & 63;
        vtile[kk][n] = vbase[(size_t)kk*512 + n];
    }
    if (t < 64) {
        a2s[t] = A2[lh*64 + t];
        qss[t] = qs[(l << 9) + (t << 3) + h];
    }
    __syncthreads();

    float cb = SC2 * S1[lh];
    size_t obase = (size_t)l*32768 + (size_t)h*4096;

    for (int j = w; j < 64; j += 8) {
        float cj = cb * qss[j];
        float s0 = cj * a2s[lane];
        float s1 = cj * a2s[lane + 32];
        if (causal) {
            if (lane > j)      s0 += -1e9f;
            if (lane + 32 > j) s1 += -1e9f;
        }
        float mx = fmaxf(s0, s1);
#pragma unroll
        for (int o = 16; o; o >>= 1) mx = fmaxf(mx, __shfl_xor_sync(0xffffffffu, mx, o));
        float e0 = expf(s0 - mx), e1 = expf(s1 - mx);
        float sum = e0 + e1;
#pragma unroll
        for (int o = 16; o; o >>= 1) sum += __shfl_xor_sync(0xffffffffu, sum, o);
        float inv = 1.f / sum;
        ps[w][lane]      = e0 * inv;
        ps[w][lane + 32] = e1 * inv;
        __syncwarp();

        float acc0 = 0.f, acc1 = 0.f;
#pragma unroll 8
        for (int kk = 0; kk < 64; kk++) {
            float p = ps[w][kk];
            acc0 = fmaf(p, vtile[kk][lane],      acc0);
            acc1 = fmaf(p, vtile[kk][lane + 32], acc1);
        }
        out[obase + j*64 + lane]      = acc0;
        out[obase + j*64 + lane + 32] = acc1;
        __syncwarp();
    }
}

// ---------------------------------------------------------------------------
// out = LayerNorm(X + Y)
// ---------------------------------------------------------------------------
__global__ void __launch_bounds__(256) k_addln(const float* __restrict__ X,
                                               const float* __restrict__ Y,
                                               float* __restrict__ out)
{
    __shared__ float rs[8], rq[8];
    int r = blockIdx.x, t = threadIdx.x;
    const float* xr = X + (size_t)r*512;
    const float* yr = Y + (size_t)r*512;
    float v0 = xr[t]       + yr[t];
    float v1 = xr[t + 256] + yr[t + 256];
    float sum = v0 + v1;
    float sq  = v0*v0 + v1*v1;
    int lane = t & 31, w = t >> 5;
#pragma unroll
    for (int o = 16; o; o >>= 1) {
        sum += __shfl_xor_sync(0xffffffffu, sum, o);
        sq  += __shfl_xor_sync(0xffffffffu, sq,  o);
    }
    if (lane == 0) { rs[w] = sum; rq[w] = sq; }
    __syncthreads();
    float ts = 0.f, tq = 0.f;
#pragma unroll
    for (int i = 0; i < 8; i++) { ts += rs[i]; tq += rq[i]; }
    float mu  = ts * (1.f/512.f);
    float var = tq * (1.f/512.f) - mu*mu;
    float inv = 1.f / sqrtf(var + 1e-5f);
    out[(size_t)r*512 + t]       = (v0 - mu) * inv;
    out[(size_t)r*512 + t + 256] = (v1 - mu) * inv;
}

// ---------------------------------------------------------------------------
// Final: out[r,:] = softmax(x[r,:] @ W_out + B_out) over 64
// ---------------------------------------------------------------------------
__global__ void __launch_bounds__(64) k_outproj(const float* __restrict__ X,
                                                const float* __restrict__ W,
                                                const float* __restrict__ b,
                                                float* __restrict__ out)
{
    __shared__ float xs[512];
    __shared__ float lg[64];
    int r = blockIdx.x, t = threadIdx.x;
    const float* xr = X + (size_t)r*512;
    for (int i = t; i < 512; i += 64) xs[i] = xr[i];
    __syncthreads();
    float acc = b[t];
#pragma unroll 8
    for (int c = 0; c < 512; c++) acc = fmaf(xs[c], W[c*64 + t], acc);
    lg[t] = acc;
    __syncthreads();
    float mx = -3.4e38f;
    for (int i = 0; i < 64; i++) mx = fmaxf(mx, lg[i]);
    __syncthreads();
    float e = expf(acc - mx);
    lg[t] = e;
    __syncthreads();
    float s = 0.f;
    for (int i = 0; i < 64; i++) s += lg[i];
    out[(size_t)r*64 + t] = e / s;
}

// ---------------------------------------------------------------------------
// Host orchestration
// ---------------------------------------------------------------------------
static void run_attn(const float* xq, const float* xk, const float* xv,
                     const float* wv, const float* wgq, const float* wgk,
                     const float* rel, int causal,
                     float* V, float* QS, float* KS, float* A2, float* S1,
                     float* OUT)
{
    k_gemm<<<dim3(4,128), 128>>>(xv, wv, nullptr, V, NROW, 512, 512, 0);
    k_qks<<<2048, 256>>>(xq, xk, wgq, wgk, QS, KS);
    k_attn_prep<<<LLEN*HN, 256>>>(rel, KS, A2, S1);
    k_attn_out<<<LLEN*HN, 256>>>(V, QS, A2, S1, OUT, causal);
}

extern "C" void kernel_launch(void* const* d_in, const int* in_sizes, int n_in,
                              void* d_out, int out_size)
{
    const float* X_en   = (const float*)d_in[0];
    const float* X_de   = (const float*)d_in[1];
    const float* W_in   = (const float*)d_in[2];
    const float* B_in   = (const float*)d_in[3];
    const float* enc_wq = (const float*)d_in[4];
    const float* enc_wk = (const float*)d_in[5];
    const float* enc_wv = (const float*)d_in[6];
    const float* enc_rel= (const float*)d_in[7];
    const float* enc_w1 = (const float*)d_in[8];
    const float* enc_b1 = (const float*)d_in[9];
    const float* enc_w2 = (const float*)d_in[10];
    const float* enc_b2 = (const float*)d_in[11];
    const float* dec_wq1= (const float*)d_in[12];
    const float* dec_wk1= (const float*)d_in[13];
    const float* dec_wv1= (const float*)d_in[14];
    const float* dec_rel1=(const float*)d_in[15];
    const float* dec_wq2= (const float*)d_in[16];
    const float* dec_wk2= (const float*)d_in[17];
    const float* dec_wv2= (const float*)d_in[18];
    const float* dec_rel2=(const float*)d_in[19];
    const float* dec_w1 = (const float*)d_in[20];
    const float* dec_b1 = (const float*)d_in[21];
    const float* dec_w2 = (const float*)d_in[22];
    const float* dec_b2 = (const float*)d_in[23];
    const float* W_out  = (const float*)d_in[24];
    const float* B_out  = (const float*)d_in[25];
    float* OUT = (float*)d_out;

    float *xen,*xde,*V,*ATT,*bufA,*bufB,*enc,*ffh,*ffo,*qs,*ks,*a2,*s1,*wg;
    cudaGetSymbolAddress((void**)&xen,  g_xen);
    cudaGetSymbolAddress((void**)&xde,  g_xde);
    cudaGetSymbolAddress((void**)&V,    g_v);
    cudaGetSymbolAddress((void**)&ATT,  g_attn);
    cudaGetSymbolAddress((void**)&bufA, g_bufA);
    cudaGetSymbolAddress((void**)&bufB, g_bufB);
    cudaGetSymbolAddress((void**)&enc,  g_enc);
    cudaGetSymbolAddress((void**)&ffh,  g_ffh);
    cudaGetSymbolAddress((void**)&ffo,  g_ffo);
    cudaGetSymbolAddress((void**)&qs,   g_qs);
    cudaGetSymbolAddress((void**)&ks,   g_ks);
    cudaGetSymbolAddress((void**)&a2,   g_a2);
    cudaGetSymbolAddress((void**)&s1,   g_s1);
    cudaGetSymbolAddress((void**)&wg,   g_wg);

    // Row-summed weights for all q/k projections (replaces 6 full GEMMs)
    k_wsum<<<16, 256>>>(enc_wq,  wg + 0*4096);
    k_wsum<<<16, 256>>>(enc_wk,  wg + 1*4096);
    k_wsum<<<16, 256>>>(dec_wq1, wg + 2*4096);
    k_wsum<<<16, 256>>>(dec_wk1, wg + 3*4096);
    k_wsum<<<16, 256>>>(dec_wq2, wg + 4*4096);
    k_wsum<<<16, 256>>>(dec_wk2, wg + 5*4096);

    // Embeddings
    k_embed<<<NROW, 128>>>(X_en, W_in, B_in, xen);
    k_embed<<<NROW, 128>>>(X_de, W_in, B_in, xde);

    // ---------------- Encoder ----------------
    run_attn(xen, xen, xen, enc_wv, wg + 0*4096, wg + 1*4096, enc_rel, 0,
             V, qs, ks, a2, s1, ATT);
    k_addln<<<NROW, 256>>>(xen, ATT, bufA);                          // o1
    k_gemm<<<dim3(16,128), 128>>>(bufA, enc_w1, enc_b1, ffh, NROW, DFF, 512, 3);
    k_gemm<<<dim3(4,128),  128>>>(ffh,  enc_w2, enc_b2, ffo, NROW, 512, DFF, 1);
    k_addln<<<NROW, 256>>>(bufA, ffo, enc);                          // enc_out

    // ---------------- Decoder self-attn (causal) ----------------
    run_attn(xde, xde, xde, dec_wv1, wg + 2*4096, wg + 3*4096, dec_rel1, 1,
             V, qs, ks, a2, s1, ATT);
    k_addln<<<NROW, 256>>>(xde, ATT, bufA);                          // m

    // ---------------- Decoder cross-attn ----------------
    run_attn(bufA, enc, enc, dec_wv2, wg + 4*4096, wg + 5*4096, dec_rel2, 0,
             V, qs, ks, a2, s1, ATT);
    k_addln<<<NROW, 256>>>(ATT, bufA, bufB);                         // c

    // ---------------- Decoder FFN ----------------
    k_gemm<<<dim3(16,128), 128>>>(bufB, dec_w1, dec_b1, ffh, NROW, DFF, 512, 3);
    k_gemm<<<dim3(4,128),  128>>>(ffh,  dec_w2, dec_b2, ffo, NROW, 512, DFF, 1);
    k_addln<<<NROW, 256>>>(bufB, ffo, bufA);

    // ---------------- Output projection + softmax ----------------
    k_outproj<<<NROW, 64>>>(bufA, W_out, B_out, OUT);

    (void)in_sizes; (void)n_in; (void)out_size;
}

// round 4
// speedup vs baseline: 2.4283x; 1.6562x over previous
#include <cuda_runtime.h>
#include <cuda_bf16.h>
#include <math.h>
#include <stdint.h>

// ---------------------------------------------------------------------------
// Problem constants
// ---------------------------------------------------------------------------
#define NROW  16384          // B*L = 64*256 (rows r = l*64 + b)
#define DMODEL 512
#define DFF   2048
#define LLEN  256
#define HN    8
#define NSEG  (NROW*8)
#define SC2   (1.0f/64.0f)

// ---------------------------------------------------------------------------
// Scratch
// ---------------------------------------------------------------------------
__device__ float g_xen [NROW*DMODEL];
__device__ float g_xde [NROW*DMODEL];
__device__ float g_v   [NROW*DMODEL];
__device__ float g_attn[NROW*DMODEL];
__device__ float g_bufA[NROW*DMODEL];
__device__ float g_bufB[NROW*DMODEL];
__device__ float g_enc [NROW*DMODEL];
__device__ float g_ffh [NROW*DFF];
__device__ float g_ffo [NROW*DMODEL];
__device__ float g_qs  [NSEG];
__device__ float g_ks  [NSEG];
__device__ float g_a2  [LLEN*HN*64];
__device__ float g_s1  [LLEN*HN];
__device__ float g_wg  [6*8*512];

// ---------------------------------------------------------------------------
// Tensor-core helpers
// ---------------------------------------------------------------------------
__device__ __forceinline__ uint32_t smem_u32(const void* p) {
    return (uint32_t)__cvta_generic_to_shared(p);
}
__device__ __forceinline__ void ldsm_x4(uint32_t* r, uint32_t addr) {
    asm volatile("ldmatrix.sync.aligned.m8n8.x4.shared.b16 {%0,%1,%2,%3}, [%4];"
        : "=r"(r[0]), "=r"(r[1]), "=r"(r[2]), "=r"(r[3]) : "r"(addr));
}
__device__ __forceinline__ void ldsm_x4t(uint32_t* r, uint32_t addr) {
    asm volatile("ldmatrix.sync.aligned.m8n8.x4.trans.shared.b16 {%0,%1,%2,%3}, [%4];"
        : "=r"(r[0]), "=r"(r[1]), "=r"(r[2]), "=r"(r[3]) : "r"(addr));
}
__device__ __forceinline__ void mma_bf16(float* c, const uint32_t* a, const uint32_t* b) {
    asm volatile(
        "mma.sync.aligned.m16n8k16.row.col.f32.bf16.bf16.f32 "
        "{%0,%1,%2,%3},{%4,%5,%6,%7},{%8,%9},{%0,%1,%2,%3};"
        : "+f"(c[0]), "+f"(c[1]), "+f"(c[2]), "+f"(c[3])
        : "r"(a[0]), "r"(a[1]), "r"(a[2]), "r"(a[3]), "r"(b[0]), "r"(b[1]));
}
__device__ __forceinline__ void bsplit(float x, unsigned short& h, unsigned short& l) {
    __nv_bfloat16 hb = __float2bfloat16(x);
    float r = x - __bfloat162float(hb);
    h = __bfloat16_as_ushort(hb);
    l = __bfloat16_as_ushort(__float2bfloat16(r));
}

// ---------------------------------------------------------------------------
// Tensor-core split-bf16 GEMM: C[M,N] = A[M,K] @ B[K,N] (+bias,+relu)
// 256 threads, tile 128x128x32, warps 2(m)x4(n), warp tile 64x32.
// A smem [m][k] padded rows (40 bf16); B smem [k][n] XOR chunk-swizzled.
// 3 mma passes: Ahi*Bhi + Alo*Bhi + Ahi*Blo  (fp32 accum).
// flags: bit0 = add bias, bit1 = relu.  Requires M%128==0, N%128==0, K%32==0.
// ---------------------------------------------------------------------------
__global__ void __launch_bounds__(256, 1) k_tgemm(const float* __restrict__ A,
                                                  const float* __restrict__ B,
                                                  const float* __restrict__ bias,
                                                  float* __restrict__ C,
                                                  int M, int N, int K, int flags)
{
    __shared__ __align__(16) unsigned short Ah[128*40];
    __shared__ __align__(16) unsigned short Al[128*40];
    __shared__ __align__(16) unsigned short Bh[32*128];
    __shared__ __align__(16) unsigned short Bl[32*128];

    const int tid = threadIdx.x;
    const int bm = blockIdx.y * 128;
    const int bn = blockIdx.x * 128;
    const int w = tid >> 5, lane = tid & 31;
    const int wm = (w >> 2) * 64;      // 0 or 64
    const int wn = (w & 3) * 32;       // 0,32,64,96
    const int g = lane >> 2, tg = lane & 3;

    // global load mappings
    const int am = tid >> 3, ak = (tid & 7) * 4;      // A rows am+32i, k-cols ak..ak+3
    const int bk = tid >> 5, bn0 = (tid & 31) * 4;    // B rows bk+8i, n-cols bn0..bn0+3

    const float* Ap = A + (size_t)(bm + am)*K + ak;
    const float* Bp = B + (size_t)bk*N + bn + bn0;

    float acc[4][4][4];
#pragma unroll
    for (int mf = 0; mf < 4; mf++)
#pragma unroll
        for (int nf = 0; nf < 4; nf++)
#pragma unroll
            for (int i = 0; i < 4; i++) acc[mf][nf][i] = 0.f;

    // ldmatrix lane-address components
    const int a_off0 = (wm + (lane & 15))*40 + (lane >> 4)*8;   // + mf*640 + ks2
    const int bkl  = (lane & 7) + ((lane >> 3) & 1)*8;          // k within 16-step
    const int bncl = lane >> 4;                                 // +0/+1 n-chunk

    const uint32_t sAh = smem_u32(Ah), sAl = smem_u32(Al);
    const uint32_t sBh = smem_u32(Bh), sBl = smem_u32(Bl);

    const int nst = K / 32;
    float4 ra[4], rb[4];
#pragma unroll
    for (int i = 0; i < 4; i++) ra[i] = *(const float4*)(Ap + (size_t)(32*i)*K);
#pragma unroll
    for (int i = 0; i < 4; i++) rb[i] = *(const float4*)(Bp + (size_t)(8*i)*N);

    for (int s = 0; s < nst; s++) {
        __syncthreads();
        // stage A (convert fp32 -> hi/lo bf16)
#pragma unroll
        for (int i = 0; i < 4; i++) {
            unsigned short h0,h1,h2,h3,l0,l1,l2,l3;
            bsplit(ra[i].x,h0,l0); bsplit(ra[i].y,h1,l1);
            bsplit(ra[i].z,h2,l2); bsplit(ra[i].w,h3,l3);
            int off = (am + 32*i)*40 + ak;
            *(uint2*)&Ah[off] = make_uint2((uint32_t)h0|((uint32_t)h1<<16),
                                           (uint32_t)h2|((uint32_t)h3<<16));
            *(uint2*)&Al[off] = make_uint2((uint32_t)l0|((uint32_t)l1<<16),
                                           (uint32_t)l2|((uint32_t)l3<<16));
        }
        // stage B
#pragma unroll
        for (int i = 0; i < 4; i++) {
            unsigned short h0,h1,h2,h3,l0,l1,l2,l3;
            bsplit(rb[i].x,h0,l0); bsplit(rb[i].y,h1,l1);
            bsplit(rb[i].z,h2,l2); bsplit(rb[i].w,h3,l3);
            int k = bk + 8*i;
            int off = k*128 + (((bn0 >> 3) ^ (k & 7)) << 3) + (bn0 & 7);
            *(uint2*)&Bh[off] = make_uint2((uint32_t)h0|((uint32_t)h1<<16),
                                           (uint32_t)h2|((uint32_t)h3<<16));
            *(uint2*)&Bl[off] = make_uint2((uint32_t)l0|((uint32_t)l1<<16),
                                           (uint32_t)l2|((uint32_t)l3<<16));
        }
        __syncthreads();

        // prefetch next stage
        if (s + 1 < nst) {
            const float* Ap2 = Ap + (s + 1)*32;
            const float* Bp2 = Bp + (size_t)(s + 1)*32*N;
#pragma unroll
            for (int i = 0; i < 4; i++) ra[i] = *(const float4*)(Ap2 + (size_t)(32*i)*K);
#pragma unroll
            for (int i = 0; i < 4; i++) rb[i] = *(const float4*)(Bp2 + (size_t)(8*i)*N);
        }

        // compute: 2 k16 steps
#pragma unroll
        for (int ks2 = 0; ks2 < 32; ks2 += 16) {
            uint32_t ah[4][4], al[4][4];
#pragma unroll
            for (int mf = 0; mf < 4; mf++) {
                int eoff = a_off0 + mf*16*40 + ks2;
                ldsm_x4(ah[mf], sAh + 2*eoff);
                ldsm_x4(al[mf], sAl + 2*eoff);
            }
            uint32_t bh[4][2], bl[4][2];
#pragma unroll
            for (int nf2 = 0; nf2 < 2; nf2++) {
                int k = ks2 + bkl;
                int nc = (wn >> 3) + nf2*2 + bncl;
                int eoff = k*128 + ((nc ^ (k & 7)) << 3);
                uint32_t r[4];
                ldsm_x4t(r, sBh + 2*eoff);
                bh[nf2*2][0] = r[0]; bh[nf2*2][1] = r[1];
                bh[nf2*2+1][0] = r[2]; bh[nf2*2+1][1] = r[3];
                ldsm_x4t(r, sBl + 2*eoff);
                bl[nf2*2][0] = r[0]; bl[nf2*2][1] = r[1];
                bl[nf2*2+1][0] = r[2]; bl[nf2*2+1][1] = r[3];
            }
#pragma unroll
            for (int mf = 0; mf < 4; mf++)
#pragma unroll
                for (int nf = 0; nf < 4; nf++) {
                    mma_bf16(acc[mf][nf], ah[mf], bh[nf]);
                    mma_bf16(acc[mf][nf], al[mf], bh[nf]);
                    mma_bf16(acc[mf][nf], ah[mf], bl[nf]);
                }
        }
    }

    // epilogue
#pragma unroll
    for (int mf = 0; mf < 4; mf++) {
#pragma unroll
        for (int nf = 0; nf < 4; nf++) {
            int row = bm + wm + mf*16 + g;
            int col = bn + wn + nf*8 + tg*2;
            float o0 = acc[mf][nf][0], o1 = acc[mf][nf][1];
            float o2 = acc[mf][nf][2], o3 = acc[mf][nf][3];
            if (flags & 1) {
                float b0 = bias[col], b1 = bias[col+1];
                o0 += b0; o1 += b1; o2 += b0; o3 += b1;
            }
            if (flags & 2) {
                o0 = fmaxf(o0,0.f); o1 = fmaxf(o1,0.f);
                o2 = fmaxf(o2,0.f); o3 = fmaxf(o3,0.f);
            }
            *(float2*)&C[(size_t)row*N + col]     = make_float2(o0, o1);
            *(float2*)&C[(size_t)(row+8)*N + col] = make_float2(o2, o3);
        }
    }
}

// ---------------------------------------------------------------------------
// Weight group-sums for all 6 q/k matrices in one launch.
// wgT[mat][g][c] = sum_{d in [g*64,(g+1)*64)} w_mat[c][d]
// ---------------------------------------------------------------------------
__global__ void __launch_bounds__(256) k_wsum6(const float* __restrict__ w0,
                                               const float* __restrict__ w1,
                                               const float* __restrict__ w2,
                                               const float* __restrict__ w3,
                                               const float* __restrict__ w4,
                                               const float* __restrict__ w5,
                                               float* __restrict__ wgT)
{
    int idx = blockIdx.x*256 + threadIdx.x;     // 0..24575
    int m = idx >> 12;
    int r = idx & 4095;
    int g = r >> 9, c = r & 511;
    const float* w = (m == 0) ? w0 : (m == 1) ? w1 : (m == 2) ? w2 :
                     (m == 3) ? w3 : (m == 4) ? w4 : w5;
    const float* p = w + (size_t)c*512 + g*64;
    float s = 0.f;
#pragma unroll 16
    for (int j = 0; j < 64; j++) s += p[j];
    wgT[m*4096 + g*512 + c] = s;
}

// ---------------------------------------------------------------------------
// qs/ks: qs[r*8+g] = sum_c xq[r,c] * wgq[g][c]
// ---------------------------------------------------------------------------
__global__ void __launch_bounds__(256) k_qks(const float* __restrict__ xq,
                                             const float* __restrict__ xk,
                                             const float* __restrict__ wgq,
                                             const float* __restrict__ wgk,
                                             float* __restrict__ qs,
                                             float* __restrict__ ks)
{
    __shared__ float sq[8][512];
    __shared__ float sk[8][512];
    int t = threadIdx.x;
    for (int i = t; i < 4096; i += 256) {
        sq[i >> 9][i & 511] = wgq[i];
        sk[i >> 9][i & 511] = wgk[i];
    }
    __syncthreads();

    int w = t >> 5, lane = t & 31;
    int r = blockIdx.x*8 + w;
    const float* xqr = xq + (size_t)r*512;
    const float* xkr = xk + (size_t)r*512;

    float aq0=0,aq1=0,aq2=0,aq3=0,aq4=0,aq5=0,aq6=0,aq7=0;
    float ak0=0,ak1=0,ak2=0,ak3=0,ak4=0,ak5=0,ak6=0,ak7=0;
#pragma unroll 4
    for (int i = 0; i < 16; i++) {
        int c = lane + 32*i;
        float xv = xqr[c];
        float kv = xkr[c];
        aq0 = fmaf(xv, sq[0][c], aq0);  ak0 = fmaf(kv, sk[0][c], ak0);
        aq1 = fmaf(xv, sq[1][c], aq1);  ak1 = fmaf(kv, sk[1][c], ak1);
        aq2 = fmaf(xv, sq[2][c], aq2);  ak2 = fmaf(kv, sk[2][c], ak2);
        aq3 = fmaf(xv, sq[3][c], aq3);  ak3 = fmaf(kv, sk[3][c], ak3);
        aq4 = fmaf(xv, sq[4][c], aq4);  ak4 = fmaf(kv, sk[4][c], ak4);
        aq5 = fmaf(xv, sq[5][c], aq5);  ak5 = fmaf(kv, sk[5][c], ak5);
        aq6 = fmaf(xv, sq[6][c], aq6);  ak6 = fmaf(kv, sk[6][c], ak6);
        aq7 = fmaf(xv, sq[7][c], aq7);  ak7 = fmaf(kv, sk[7][c], ak7);
    }
#pragma unroll
    for (int o = 16; o; o >>= 1) {
        aq0 += __shfl_xor_sync(~0u, aq0, o);  ak0 += __shfl_xor_sync(~0u, ak0, o);
        aq1 += __shfl_xor_sync(~0u, aq1, o);  ak1 += __shfl_xor_sync(~0u, ak1, o);
        aq2 += __shfl_xor_sync(~0u, aq2, o);  ak2 += __shfl_xor_sync(~0u, ak2, o);
        aq3 += __shfl_xor_sync(~0u, aq3, o);  ak3 += __shfl_xor_sync(~0u, ak3, o);
        aq4 += __shfl_xor_sync(~0u, aq4, o);  ak4 += __shfl_xor_sync(~0u, ak4, o);
        aq5 += __shfl_xor_sync(~0u, aq5, o);  ak5 += __shfl_xor_sync(~0u, ak5, o);
        aq6 += __shfl_xor_sync(~0u, aq6, o);  ak6 += __shfl_xor_sync(~0u, ak6, o);
        aq7 += __shfl_xor_sync(~0u, aq7, o);  ak7 += __shfl_xor_sync(~0u, ak7, o);
    }
    if (lane == 0) {
        float* q = qs + r*8;
        q[0]=aq0; q[1]=aq1; q[2]=aq2; q[3]=aq3; q[4]=aq4; q[5]=aq5; q[6]=aq6; q[7]=aq7;
    } else if (lane == 1) {
        float* k = ks + r*8;
        k[0]=ak0; k[1]=ak1; k[2]=ak2; k[3]=ak3; k[4]=ak4; k[5]=ak5; k[6]=ak6; k[7]=ak7;
    }
}

// ---------------------------------------------------------------------------
// Attention prep (per (l,h))
// ---------------------------------------------------------------------------
__global__ void __launch_bounds__(256) k_attn_prep(const float* __restrict__ rel,
                                                   const float* __restrict__ ks,
                                                   float* __restrict__ A2,
                                                   float* __restrict__ S1)
{
    __shared__ float tile[4096];
    __shared__ float kss[64];
    __shared__ float a1p[64][4];
    __shared__ float a2p[64][4];

    int lh = blockIdx.x;
    int l  = lh >> 3, h = lh & 7;
    int t  = threadIdx.x;

    const float* rp = rel + (size_t)lh*4096;
    for (int i = t; i < 4096; i += 256) tile[i] = rp[i];
    if (t < 64) kss[t] = ks[(l << 9) + (t << 3) + h];
    __syncthreads();

    int kk = t & 63, q = t >> 6;
    float a1 = 0.f, a2 = 0.f;
    int base = 127*kk + 63;
    for (int m = q*16; m < q*16 + 16; m++) {
        int p = base + m;
        int c = p & 127;
        if (c < 64) {
            float a = tile[((p >> 7) << 6) + c];
            float km = kss[m];
            a1 = fmaf(km, a, a1);
            a2 = fmaf(km - 1e9f*(float)m, a, a2);
        }
    }
    a1p[kk][q] = a1;
    a2p[kk][q] = a2;
    __syncthreads();

    if (t < 64) {
        float A1v = a1p[t][0] + a1p[t][1] + a1p[t][2] + a1p[t][3];
        float A2v = a2p[t][0] + a2p[t][1] + a2p[t][2] + a2p[t][3];
        A2[lh*64 + t] = A2v;
        a1p[t][0] = A1v;
    }
    __syncthreads();
    if (t == 0) {
        float s = 0.f;
        for (int i = 0; i < 64; i++) s += a1p[i][0];
        S1[lh] = s;
    }
}

// ---------------------------------------------------------------------------
// Attention softmax + PV (per (l,h))
// ---------------------------------------------------------------------------
__global__ void __launch_bounds__(256) k_attn_out(const float* __restrict__ Yv,
                                                  const float* __restrict__ qs,
                                                  const float* __restrict__ A2,
                                                  const float* __restrict__ S1,
                                                  float* __restrict__ out,
                                                  int causal)
{
    __shared__ float vtile[64][64];
    __shared__ float a2s[64];
    __shared__ float qss[64];
    __shared__ float ps[8][64];

    int lh = blockIdx.x;
    int l = lh >> 3, h = lh & 7;
    int t = threadIdx.x, w = t >> 5, lane = t & 31;

    const float* vbase = Yv + (size_t)l*32768 + h*64;
    for (int i = t; i < 4096; i += 256) {
        int kk = i >> 6, n = i & 63;
        vtile[kk][n] = vbase[(size_t)kk*512 + n];
    }
    if (t < 64) {
        a2s[t] = A2[lh*64 + t];
        qss[t] = qs[(l << 9) + (t << 3) + h];
    }
    __syncthreads();

    float cb = SC2 * S1[lh];
    size_t obase = (size_t)l*32768 + (size_t)h*4096;

    for (int j = w; j < 64; j += 8) {
        float cj = cb * qss[j];
        float s0 = cj * a2s[lane];
        float s1 = cj * a2s[lane + 32];
        if (causal) {
            if (lane > j)      s0 += -1e9f;
            if (lane + 32 > j) s1 += -1e9f;
        }
        float mx = fmaxf(s0, s1);
#pragma unroll
        for (int o = 16; o; o >>= 1) mx = fmaxf(mx, __shfl_xor_sync(0xffffffffu, mx, o));
        float e0 = expf(s0 - mx), e1 = expf(s1 - mx);
        float sum = e0 + e1;
#pragma unroll
        for (int o = 16; o; o >>= 1) sum += __shfl_xor_sync(0xffffffffu, sum, o);
        float inv = 1.f / sum;
        ps[w][lane]      = e0 * inv;
        ps[w][lane + 32] = e1 * inv;
        __syncwarp();

        float acc0 = 0.f, acc1 = 0.f;
#pragma unroll 8
        for (int kk = 0; kk < 64; kk++) {
            float p = ps[w][kk];
            acc0 = fmaf(p, vtile[kk][lane],      acc0);
            acc1 = fmaf(p, vtile[kk][lane + 32], acc1);
        }
        out[obase + j*64 + lane]      = acc0;
        out[obase + j*64 + lane + 32] = acc1;
        __syncwarp();
    }
}

// ---------------------------------------------------------------------------
// out = LayerNorm(X + Y)
// ---------------------------------------------------------------------------
__global__ void __launch_bounds__(256) k_addln(const float* __restrict__ X,
                                               const float* __restrict__ Y,
                                               float* __restrict__ out)
{
    __shared__ float rs[8], rq[8];
    int r = blockIdx.x, t = threadIdx.x;
    const float* xr = X + (size_t)r*512;
    const float* yr = Y + (size_t)r*512;
    float v0 = xr[t]       + yr[t];
    float v1 = xr[t + 256] + yr[t + 256];
    float sum = v0 + v1;
    float sq  = v0*v0 + v1*v1;
    int lane = t & 31, w = t >> 5;
#pragma unroll
    for (int o = 16; o; o >>= 1) {
        sum += __shfl_xor_sync(0xffffffffu, sum, o);
        sq  += __shfl_xor_sync(0xffffffffu, sq,  o);
    }
    if (lane == 0) { rs[w] = sum; rq[w] = sq; }
    __syncthreads();
    float ts = 0.f, tq = 0.f;
#pragma unroll
    for (int i = 0; i < 8; i++) { ts += rs[i]; tq += rq[i]; }
    float mu  = ts * (1.f/512.f);
    float var = tq * (1.f/512.f) - mu*mu;
    float inv = 1.f / sqrtf(var + 1e-5f);
    out[(size_t)r*512 + t]       = (v0 - mu) * inv;
    out[(size_t)r*512 + t + 256] = (v1 - mu) * inv;
}

// ---------------------------------------------------------------------------
// Final: out[r,:] = softmax(x[r,:] @ W_out + B_out) over 64
// ---------------------------------------------------------------------------
__global__ void __launch_bounds__(64) k_outproj(const float* __restrict__ X,
                                                const float* __restrict__ W,
                                                const float* __restrict__ b,
                                                float* __restrict__ out)
{
    __shared__ float xs[512];
    __shared__ float lg[64];
    int r = blockIdx.x, t = threadIdx.x;
    const float* xr = X + (size_t)r*512;
    for (int i = t; i < 512; i += 64) xs[i] = xr[i];
    __syncthreads();
    float acc = b[t];
#pragma unroll 8
    for (int c = 0; c < 512; c++) acc = fmaf(xs[c], W[c*64 + t], acc);
    lg[t] = acc;
    __syncthreads();
    float mx = -3.4e38f;
    for (int i = 0; i < 64; i++) mx = fmaxf(mx, lg[i]);
    __syncthreads();
    float e = expf(acc - mx);
    lg[t] = e;
    __syncthreads();
    float s = 0.f;
    for (int i = 0; i < 64; i++) s += lg[i];
    out[(size_t)r*64 + t] = e / s;
}

// ---------------------------------------------------------------------------
// Host orchestration
// ---------------------------------------------------------------------------
static void run_attn(const float* xq, const float* xk, const float* xv,
                     const float* wv, const float* wgq, const float* wgk,
                     const float* rel, int causal,
                     float* V, float* QS, float* KS, float* A2, float* S1,
                     float* OUT)
{
    k_tgemm<<<dim3(4,128), 256>>>(xv, wv, nullptr, V, NROW, 512, 512, 0);
    k_qks<<<2048, 256>>>(xq, xk, wgq, wgk, QS, KS);
    k_attn_prep<<<LLEN*HN, 256>>>(rel, KS, A2, S1);
    k_attn_out<<<LLEN*HN, 256>>>(V, QS, A2, S1, OUT, causal);
}

extern "C" void kernel_launch(void* const* d_in, const int* in_sizes, int n_in,
                              void* d_out, int out_size)
{
    const float* X_en   = (const float*)d_in[0];
    const float* X_de   = (const float*)d_in[1];
    const float* W_in   = (const float*)d_in[2];
    const float* B_in   = (const float*)d_in[3];
    const float* enc_wq = (const float*)d_in[4];
    const float* enc_wk = (const float*)d_in[5];
    const float* enc_wv = (const float*)d_in[6];
    const float* enc_rel= (const float*)d_in[7];
    const float* enc_w1 = (const float*)d_in[8];
    const float* enc_b1 = (const float*)d_in[9];
    const float* enc_w2 = (const float*)d_in[10];
    const float* enc_b2 = (const float*)d_in[11];
    const float* dec_wq1= (const float*)d_in[12];
    const float* dec_wk1= (const float*)d_in[13];
    const float* dec_wv1= (const float*)d_in[14];
    const float* dec_rel1=(const float*)d_in[15];
    const float* dec_wq2= (const float*)d_in[16];
    const float* dec_wk2= (const float*)d_in[17];
    const float* dec_wv2= (const float*)d_in[18];
    const float* dec_rel2=(const float*)d_in[19];
    const float* dec_w1 = (const float*)d_in[20];
    const float* dec_b1 = (const float*)d_in[21];
    const float* dec_w2 = (const float*)d_in[22];
    const float* dec_b2 = (const float*)d_in[23];
    const float* W_out  = (const float*)d_in[24];
    const float* B_out  = (const float*)d_in[25];
    float* OUT = (float*)d_out;

    float *xen,*xde,*V,*ATT,*bufA,*bufB,*enc,*ffh,*ffo,*qs,*ks,*a2,*s1,*wg;
    cudaGetSymbolAddress((void**)&xen,  g_xen);
    cudaGetSymbolAddress((void**)&xde,  g_xde);
    cudaGetSymbolAddress((void**)&V,    g_v);
    cudaGetSymbolAddress((void**)&ATT,  g_attn);
    cudaGetSymbolAddress((void**)&bufA, g_bufA);
    cudaGetSymbolAddress((void**)&bufB, g_bufB);
    cudaGetSymbolAddress((void**)&enc,  g_enc);
    cudaGetSymbolAddress((void**)&ffh,  g_ffh);
    cudaGetSymbolAddress((void**)&ffo,  g_ffo);
    cudaGetSymbolAddress((void**)&qs,   g_qs);
    cudaGetSymbolAddress((void**)&ks,   g_ks);
    cudaGetSymbolAddress((void**)&a2,   g_a2);
    cudaGetSymbolAddress((void**)&s1,   g_s1);
    cudaGetSymbolAddress((void**)&wg,   g_wg);

    // Row-summed q/k weights (replaces 6 projection GEMMs), one launch
    k_wsum6<<<96, 256>>>(enc_wq, enc_wk, dec_wq1, dec_wk1, dec_wq2, dec_wk2, wg);

    // Embeddings as tensor GEMMs (raw reshape A: [16384 x 64])
    k_tgemm<<<dim3(4,128), 256>>>(X_en, W_in, B_in, xen, NROW, 512, 64, 1);
    k_tgemm<<<dim3(4,128), 256>>>(X_de, W_in, B_in, xde, NROW, 512, 64, 1);

    // ---------------- Encoder ----------------
    run_attn(xen, xen, xen, enc_wv, wg + 0*4096, wg + 1*4096, enc_rel, 0,
             V, qs, ks, a2, s1, ATT);
    k_addln<<<NROW, 256>>>(xen, ATT, bufA);                          // o1
    k_tgemm<<<dim3(16,128), 256>>>(bufA, enc_w1, enc_b1, ffh, NROW, DFF, 512, 3);
    k_tgemm<<<dim3(4,128),  256>>>(ffh,  enc_w2, enc_b2, ffo, NROW, 512, DFF, 1);
    k_addln<<<NROW, 256>>>(bufA, ffo, enc);                          // enc_out

    // ---------------- Decoder self-attn (causal) ----------------
    run_attn(xde, xde, xde, dec_wv1, wg + 2*4096, wg + 3*4096, dec_rel1, 1,
             V, qs, ks, a2, s1, ATT);
    k_addln<<<NROW, 256>>>(xde, ATT, bufA);                          // m

    // ---------------- Decoder cross-attn ----------------
    run_attn(bufA, enc, enc, dec_wv2, wg + 4*4096, wg + 5*4096, dec_rel2, 0,
             V, qs, ks, a2, s1, ATT);
    k_addln<<<NROW, 256>>>(ATT, bufA, bufB);                         // c

    // ---------------- Decoder FFN ----------------
    k_tgemm<<<dim3(16,128), 256>>>(bufB, dec_w1, dec_b1, ffh, NROW, DFF, 512, 3);
    k_tgemm<<<dim3(4,128),  256>>>(ffh,  dec_w2, dec_b2, ffo, NROW, 512, DFF, 1);
    k_addln<<<NROW, 256>>>(bufB, ffo, bufA);

    // ---------------- Output projection + softmax ----------------
    k_outproj<<<NROW, 64>>>(bufA, W_out, B_out, OUT);

    (void)in_sizes; (void)n_in; (void)out_size;
}

// round 5
// speedup vs baseline: 2.8053x; 1.1553x over previous
#include <cuda_runtime.h>
#include <cuda_bf16.h>
#include <math.h>
#include <stdint.h>

// ---------------------------------------------------------------------------
// Problem constants
// ---------------------------------------------------------------------------
#define NROW  16384
#define DMODEL 512
#define DFF   2048
#define LLEN  256
#define HN    8
#define NSEG  (NROW*8)
#define SC2   (1.0f/64.0f)

// ---------------------------------------------------------------------------
// Scratch (fp32)
// ---------------------------------------------------------------------------
__device__ float g_xen [NROW*DMODEL];
__device__ float g_xde [NROW*DMODEL];
__device__ float g_v   [NROW*DMODEL];
__device__ float g_attn[NROW*DMODEL];
__device__ float g_bufA[NROW*DMODEL];
__device__ float g_bufB[NROW*DMODEL];
__device__ float g_enc [NROW*DMODEL];
__device__ float g_ffo [NROW*DMODEL];
__device__ float g_qs  [NSEG];
__device__ float g_ks  [NSEG];
__device__ float g_a2  [LLEN*HN*64];
__device__ float g_s1  [LLEN*HN];
__device__ float g_wg  [6*8*512];

// Split bf16 buffers (hi/lo)
__device__ __nv_bfloat16 g_sxen_h[4194304], g_sxen_l[4194304];
__device__ __nv_bfloat16 g_sxde_h[4194304], g_sxde_l[4194304];
__device__ __nv_bfloat16 g_xen_h [NROW*DMODEL], g_xen_l [NROW*DMODEL];
__device__ __nv_bfloat16 g_xde_h [NROW*DMODEL], g_xde_l [NROW*DMODEL];
__device__ __nv_bfloat16 g_enc_h [NROW*DMODEL], g_enc_l [NROW*DMODEL];
__device__ __nv_bfloat16 g_bufA_h[NROW*DMODEL], g_bufA_l[NROW*DMODEL];
__device__ __nv_bfloat16 g_bufB_h[NROW*DMODEL], g_bufB_l[NROW*DMODEL];
__device__ __nv_bfloat16 g_ffh_h [NROW*DFF],    g_ffh_l [NROW*DFF];
__device__ __nv_bfloat16 g_win_h [32768],       g_win_l [32768];
#define NWSPLIT 4980736
__device__ __nv_bfloat16 g_wsp_h[NWSPLIT], g_wsp_l[NWSPLIT];
// weight split offsets
#define WV0 0
#define WV1 262144
#define WV2 524288
#define W1E 786432
#define W2E 1835008
#define W1D 2883584
#define W2D 3932160

// ---------------------------------------------------------------------------
// Helpers
// ---------------------------------------------------------------------------
__device__ __forceinline__ uint32_t smem_u32(const void* p) {
    return (uint32_t)__cvta_generic_to_shared(p);
}
__device__ __forceinline__ void ldsm_x4(uint32_t* r, uint32_t addr) {
    asm volatile("ldmatrix.sync.aligned.m8n8.x4.shared.b16 {%0,%1,%2,%3}, [%4];"
        : "=r"(r[0]), "=r"(r[1]), "=r"(r[2]), "=r"(r[3]) : "r"(addr));
}
__device__ __forceinline__ void ldsm_x4t(uint32_t* r, uint32_t addr) {
    asm volatile("ldmatrix.sync.aligned.m8n8.x4.trans.shared.b16 {%0,%1,%2,%3}, [%4];"
        : "=r"(r[0]), "=r"(r[1]), "=r"(r[2]), "=r"(r[3]) : "r"(addr));
}
__device__ __forceinline__ void mma_bf16(float* c, const uint32_t* a, const uint32_t* b) {
    asm volatile(
        "mma.sync.aligned.m16n8k16.row.col.f32.bf16.bf16.f32 "
        "{%0,%1,%2,%3},{%4,%5,%6,%7},{%8,%9},{%0,%1,%2,%3};"
        : "+f"(c[0]), "+f"(c[1]), "+f"(c[2]), "+f"(c[3])
        : "r"(a[0]), "r"(a[1]), "r"(a[2]), "r"(a[3]), "r"(b[0]), "r"(b[1]));
}
__device__ __forceinline__ void cp16(uint32_t dst, const void* src) {
    asm volatile("cp.async.cg.shared.global [%0], [%1], 16;" :: "r"(dst), "l"(src));
}
__device__ __forceinline__ void cp_commit() {
    asm volatile("cp.async.commit_group;");
}
template<int N> __device__ __forceinline__ void cp_wait() {
    asm volatile("cp.async.wait_group %0;" :: "n"(N));
}
__device__ __forceinline__ void bsplit(float x, unsigned short& h, unsigned short& l) {
    __nv_bfloat16 hb = __float2bfloat16(x);
    float r = x - __bfloat162float(hb);
    h = __bfloat16_as_ushort(hb);
    l = __bfloat16_as_ushort(__float2bfloat16(r));
}
__device__ __forceinline__ void bsplit2(float a, float b, uint32_t& hh, uint32_t& ll) {
    unsigned short h0,l0,h1,l1;
    bsplit(a,h0,l0); bsplit(b,h1,l1);
    hh = (uint32_t)h0 | ((uint32_t)h1 << 16);
    ll = (uint32_t)l0 | ((uint32_t)l1 << 16);
}

// ---------------------------------------------------------------------------
// k_split: fp32 -> (hi,lo) bf16.  n % 1024 == 0.
// ---------------------------------------------------------------------------
__global__ void __launch_bounds__(256) k_split(const float* __restrict__ x,
                                               __nv_bfloat16* __restrict__ hi,
                                               __nv_bfloat16* __restrict__ lo,
                                               int n)
{
    int i = (blockIdx.x*256 + threadIdx.x)*4;
    if (i >= n) return;
    float4 v = *(const float4*)(x + i);
    uint32_t h0,l0,h1,l1;
    bsplit2(v.x, v.y, h0, l0);
    bsplit2(v.z, v.w, h1, l1);
    *(uint2*)&hi[i] = make_uint2(h0, h1);
    *(uint2*)&lo[i] = make_uint2(l0, l1);
}

// ---------------------------------------------------------------------------
// Pipelined split-bf16 tensor GEMM.
// A = Ah+Al [M,K] row-major bf16 pair; B = Bh+Bl [K,N] row-major bf16 pair.
// Tile 128x128x32, 256 threads, warps 2(m)x4(n), 3-stage cp.async pipeline.
// flags: b0 bias, b1 relu, b2 write split (Ch,Cl), b3 skip fp32 C.
// ---------------------------------------------------------------------------
#define STAGE_BYTES 36864
#define OFF_AL 10240
#define OFF_BH 20480
#define OFF_BL 28672

extern __shared__ char dsm[];

__device__ __forceinline__ void ld_stage(uint32_t sb,
    const __nv_bfloat16* __restrict__ Ah, const __nv_bfloat16* __restrict__ Al,
    const __nv_bfloat16* __restrict__ Bh, const __nv_bfloat16* __restrict__ Bl,
    int K, int N, int bm, int bn, int tid, int k0)
{
    int rowA = tid >> 2, kc = tid & 3;
    size_t aoff0 = (size_t)(bm + rowA)*K + k0 + kc*8;
    size_t aoff1 = aoff0 + (size_t)64*K;
    uint32_t dA = sb + rowA*80 + kc*16;
    cp16(dA,            Ah + aoff0);
    cp16(dA + 64*80,    Ah + aoff1);
    cp16(dA + OFF_AL,         Al + aoff0);
    cp16(dA + OFF_AL + 64*80, Al + aoff1);

    int kr = tid >> 4, nc = tid & 15;
    size_t boff0 = (size_t)(k0 + kr)*N + bn + nc*8;
    size_t boff1 = boff0 + (size_t)16*N;
    uint32_t dB0 = sb + OFF_BH + kr*256 + ((nc ^ (kr & 7)) << 4);
    uint32_t dB1 = sb + OFF_BH + (kr+16)*256 + ((nc ^ ((kr+16) & 7)) << 4);
    cp16(dB0, Bh + boff0);
    cp16(dB1, Bh + boff1);
    cp16(dB0 + 8192, Bl + boff0);
    cp16(dB1 + 8192, Bl + boff1);
}

__global__ void __launch_bounds__(256, 1) k_bgemm(
    const __nv_bfloat16* __restrict__ Ah, const __nv_bfloat16* __restrict__ Al,
    const __nv_bfloat16* __restrict__ Bh, const __nv_bfloat16* __restrict__ Bl,
    const float* __restrict__ bias, float* __restrict__ C,
    __nv_bfloat16* __restrict__ Ch, __nv_bfloat16* __restrict__ Cl,
    int M, int N, int K, int flags)
{
    const int tid = threadIdx.x;
    const int bm = blockIdx.y * 128;
    const int bn = blockIdx.x * 128;
    const int w = tid >> 5, lane = tid & 31;
    const int wm = (w >> 2) * 64;
    const int wn = (w & 3) * 32;
    const int g = lane >> 2, tg = lane & 3;
    const uint32_t sbase = smem_u32(dsm);

    float acc[4][4][4];
#pragma unroll
    for (int mf = 0; mf < 4; mf++)
#pragma unroll
        for (int nf = 0; nf < 4; nf++)
#pragma unroll
            for (int i = 0; i < 4; i++) acc[mf][nf][i] = 0.f;

    const int a_off0 = (wm + (lane & 15))*40 + (lane >> 4)*8;
    const int bkl  = (lane & 7) + ((lane >> 3) & 1)*8;
    const int bncl = lane >> 4;

    const int T = K / 32;

    // prologue: stages 0,1
    ld_stage(sbase,               Ah, Al, Bh, Bl, K, N, bm, bn, tid, 0);
    cp_commit();
    ld_stage(sbase + STAGE_BYTES, Ah, Al, Bh, Bl, K, N, bm, bn, tid, 32);
    cp_commit();

    for (int kt = 0; kt < T; ++kt) {
        cp_wait<1>();
        __syncthreads();

        if (kt + 2 < T) {
            int buf = (kt + 2) % 3;
            ld_stage(sbase + buf*STAGE_BYTES, Ah, Al, Bh, Bl, K, N, bm, bn,
                     tid, (kt + 2)*32);
        }
        cp_commit();

        const uint32_t bA = sbase + (kt % 3)*STAGE_BYTES;
        const uint32_t bB = bA + OFF_BH;
#pragma unroll
        for (int ks2 = 0; ks2 < 32; ks2 += 16) {
            uint32_t ah[4][4], al[4][4];
#pragma unroll
            for (int mf = 0; mf < 4; mf++) {
                int eoff = a_off0 + mf*640 + ks2;
                ldsm_x4(ah[mf], bA + 2*eoff);
                ldsm_x4(al[mf], bA + OFF_AL + 2*eoff);
            }
            uint32_t bh[4][2], bl[4][2];
#pragma unroll
            for (int nf2 = 0; nf2 < 2; nf2++) {
                int k = ks2 + bkl;
                int nc = (wn >> 3) + nf2*2 + bncl;
                int eoff = k*128 + ((nc ^ (k & 7)) << 3);
                uint32_t r[4];
                ldsm_x4t(r, bB + 2*eoff);
                bh[nf2*2][0] = r[0]; bh[nf2*2][1] = r[1];
                bh[nf2*2+1][0] = r[2]; bh[nf2*2+1][1] = r[3];
                ldsm_x4t(r, bB + 8192 + 2*eoff);
                bl[nf2*2][0] = r[0]; bl[nf2*2][1] = r[1];
                bl[nf2*2+1][0] = r[2]; bl[nf2*2+1][1] = r[3];
            }
#pragma unroll
            for (int mf = 0; mf < 4; mf++)
#pragma unroll
                for (int nf = 0; nf < 4; nf++) {
                    mma_bf16(acc[mf][nf], ah[mf], bh[nf]);
                    mma_bf16(acc[mf][nf], al[mf], bh[nf]);
                    mma_bf16(acc[mf][nf], ah[mf], bl[nf]);
                }
        }
    }

    // epilogue
#pragma unroll
    for (int mf = 0; mf < 4; mf++) {
#pragma unroll
        for (int nf = 0; nf < 4; nf++) {
            int row = bm + wm + mf*16 + g;
            int col = bn + wn + nf*8 + tg*2;
            float o0 = acc[mf][nf][0], o1 = acc[mf][nf][1];
            float o2 = acc[mf][nf][2], o3 = acc[mf][nf][3];
            if (flags & 1) {
                float b0 = bias[col], b1 = bias[col+1];
                o0 += b0; o1 += b1; o2 += b0; o3 += b1;
            }
            if (flags & 2) {
                o0 = fmaxf(o0,0.f); o1 = fmaxf(o1,0.f);
                o2 = fmaxf(o2,0.f); o3 = fmaxf(o3,0.f);
            }
            size_t i0 = (size_t)row*N + col;
            size_t i1 = (size_t)(row+8)*N + col;
            if (!(flags & 8)) {
                *(float2*)&C[i0] = make_float2(o0, o1);
                *(float2*)&C[i1] = make_float2(o2, o3);
            }
            if (flags & 4) {
                uint32_t hh, ll;
                bsplit2(o0, o1, hh, ll);
                *(uint32_t*)&Ch[i0] = hh;
                *(uint32_t*)&Cl[i0] = ll;
                bsplit2(o2, o3, hh, ll);
                *(uint32_t*)&Ch[i1] = hh;
                *(uint32_t*)&Cl[i1] = ll;
            }
        }
    }
}

// ---------------------------------------------------------------------------
// Weight group-sums (6 q/k matrices)
// ---------------------------------------------------------------------------
__global__ void __launch_bounds__(256) k_wsum6(const float* __restrict__ w0,
                                               const float* __restrict__ w1,
                                               const float* __restrict__ w2,
                                               const float* __restrict__ w3,
                                               const float* __restrict__ w4,
                                               const float* __restrict__ w5,
                                               float* __restrict__ wgT)
{
    int idx = blockIdx.x*256 + threadIdx.x;
    int m = idx >> 12;
    int r = idx & 4095;
    int g = r >> 9, c = r & 511;
    const float* w = (m == 0) ? w0 : (m == 1) ? w1 : (m == 2) ? w2 :
                     (m == 3) ? w3 : (m == 4) ? w4 : w5;
    const float* p = w + (size_t)c*512 + g*64;
    float s = 0.f;
#pragma unroll 16
    for (int j = 0; j < 64; j++) s += p[j];
    wgT[m*4096 + g*512 + c] = s;
}

// ---------------------------------------------------------------------------
// qs/ks
// ---------------------------------------------------------------------------
__global__ void __launch_bounds__(256) k_qks(const float* __restrict__ xq,
                                             const float* __restrict__ xk,
                                             const float* __restrict__ wgq,
                                             const float* __restrict__ wgk,
                                             float* __restrict__ qs,
                                             float* __restrict__ ks)
{
    __shared__ float sq[8][512];
    __shared__ float sk[8][512];
    int t = threadIdx.x;
    for (int i = t; i < 4096; i += 256) {
        sq[i >> 9][i & 511] = wgq[i];
        sk[i >> 9][i & 511] = wgk[i];
    }
    __syncthreads();

    int w = t >> 5, lane = t & 31;
    int r = blockIdx.x*8 + w;
    const float* xqr = xq + (size_t)r*512;
    const float* xkr = xk + (size_t)r*512;

    float aq0=0,aq1=0,aq2=0,aq3=0,aq4=0,aq5=0,aq6=0,aq7=0;
    float ak0=0,ak1=0,ak2=0,ak3=0,ak4=0,ak5=0,ak6=0,ak7=0;
#pragma unroll 4
    for (int i = 0; i < 16; i++) {
        int c = lane + 32*i;
        float xv = xqr[c];
        float kv = xkr[c];
        aq0 = fmaf(xv, sq[0][c], aq0);  ak0 = fmaf(kv, sk[0][c], ak0);
        aq1 = fmaf(xv, sq[1][c], aq1);  ak1 = fmaf(kv, sk[1][c], ak1);
        aq2 = fmaf(xv, sq[2][c], aq2);  ak2 = fmaf(kv, sk[2][c], ak2);
        aq3 = fmaf(xv, sq[3][c], aq3);  ak3 = fmaf(kv, sk[3][c], ak3);
        aq4 = fmaf(xv, sq[4][c], aq4);  ak4 = fmaf(kv, sk[4][c], ak4);
        aq5 = fmaf(xv, sq[5][c], aq5);  ak5 = fmaf(kv, sk[5][c], ak5);
        aq6 = fmaf(xv, sq[6][c], aq6);  ak6 = fmaf(kv, sk[6][c], ak6);
        aq7 = fmaf(xv, sq[7][c], aq7);  ak7 = fmaf(kv, sk[7][c], ak7);
    }
#pragma unroll
    for (int o = 16; o; o >>= 1) {
        aq0 += __shfl_xor_sync(~0u, aq0, o);  ak0 += __shfl_xor_sync(~0u, ak0, o);
        aq1 += __shfl_xor_sync(~0u, aq1, o);  ak1 += __shfl_xor_sync(~0u, ak1, o);
        aq2 += __shfl_xor_sync(~0u, aq2, o);  ak2 += __shfl_xor_sync(~0u, ak2, o);
        aq3 += __shfl_xor_sync(~0u, aq3, o);  ak3 += __shfl_xor_sync(~0u, ak3, o);
        aq4 += __shfl_xor_sync(~0u, aq4, o);  ak4 += __shfl_xor_sync(~0u, ak4, o);
        aq5 += __shfl_xor_sync(~0u, aq5, o);  ak5 += __shfl_xor_sync(~0u, ak5, o);
        aq6 += __shfl_xor_sync(~0u, aq6, o);  ak6 += __shfl_xor_sync(~0u, ak6, o);
        aq7 += __shfl_xor_sync(~0u, aq7, o);  ak7 += __shfl_xor_sync(~0u, ak7, o);
    }
    if (lane == 0) {
        float* q = qs + r*8;
        q[0]=aq0; q[1]=aq1; q[2]=aq2; q[3]=aq3; q[4]=aq4; q[5]=aq5; q[6]=aq6; q[7]=aq7;
    } else if (lane == 1) {
        float* k = ks + r*8;
        k[0]=ak0; k[1]=ak1; k[2]=ak2; k[3]=ak3; k[4]=ak4; k[5]=ak5; k[6]=ak6; k[7]=ak7;
    }
}

// ---------------------------------------------------------------------------
// Attention prep
// ---------------------------------------------------------------------------
__global__ void __launch_bounds__(256) k_attn_prep(const float* __restrict__ rel,
                                                   const float* __restrict__ ks,
                                                   float* __restrict__ A2,
                                                   float* __restrict__ S1)
{
    __shared__ float tile[4096];
    __shared__ float kss[64];
    __shared__ float a1p[64][4];
    __shared__ float a2p[64][4];

    int lh = blockIdx.x;
    int l  = lh >> 3, h = lh & 7;
    int t  = threadIdx.x;

    const float* rp = rel + (size_t)lh*4096;
    for (int i = t; i < 4096; i += 256) tile[i] = rp[i];
    if (t < 64) kss[t] = ks[(l << 9) + (t << 3) + h];
    __syncthreads();

    int kk = t & 63, q = t >> 6;
    float a1 = 0.f, a2 = 0.f;
    int base = 127*kk + 63;
    for (int m = q*16; m < q*16 + 16; m++) {
        int p = base + m;
        int c = p & 127;
        if (c < 64) {
            float a = tile[((p >> 7) << 6) + c];
            float km = kss[m];
            a1 = fmaf(km, a, a1);
            a2 = fmaf(km - 1e9f*(float)m, a, a2);
        }
    }
    a1p[kk][q] = a1;
    a2p[kk][q] = a2;
    __syncthreads();

    if (t < 64) {
        float A1v = a1p[t][0] + a1p[t][1] + a1p[t][2] + a1p[t][3];
        float A2v = a2p[t][0] + a2p[t][1] + a2p[t][2] + a2p[t][3];
        A2[lh*64 + t] = A2v;
        a1p[t][0] = A1v;
    }
    __syncthreads();
    if (t == 0) {
        float s = 0.f;
        for (int i = 0; i < 64; i++) s += a1p[i][0];
        S1[lh] = s;
    }
}

// ---------------------------------------------------------------------------
// Attention softmax + PV
// ---------------------------------------------------------------------------
__global__ void __launch_bounds__(256) k_attn_out(const float* __restrict__ Yv,
                                                  const float* __restrict__ qs,
                                                  const float* __restrict__ A2,
                                                  const float* __restrict__ S1,
                                                  float* __restrict__ out,
                                                  int causal)
{
    __shared__ float vtile[64][64];
    __shared__ float a2s[64];
    __shared__ float qss[64];
    __shared__ float ps[8][64];

    int lh = blockIdx.x;
    int l = lh >> 3, h = lh & 7;
    int t = threadIdx.x, w = t >> 5, lane = t & 31;

    const float* vbase = Yv + (size_t)l*32768 + h*64;
    for (int i = t; i < 4096; i += 256) {
        int kk = i >> 6, n = i & 63;
        vtile[kk][n] = vbase[(size_t)kk*512 + n];
    }
    if (t < 64) {
        a2s[t] = A2[lh*64 + t];
        qss[t] = qs[(l << 9) + (t << 3) + h];
    }
    __syncthreads();

    float cb = SC2 * S1[lh];
    size_t obase = (size_t)l*32768 + (size_t)h*4096;

    for (int j = w; j < 64; j += 8) {
        float cj = cb * qss[j];
        float s0 = cj * a2s[lane];
        float s1 = cj * a2s[lane + 32];
        if (causal) {
            if (lane > j)      s0 += -1e9f;
            if (lane + 32 > j) s1 += -1e9f;
        }
        float mx = fmaxf(s0, s1);
#pragma unroll
        for (int o = 16; o; o >>= 1) mx = fmaxf(mx, __shfl_xor_sync(0xffffffffu, mx, o));
        float e0 = expf(s0 - mx), e1 = expf(s1 - mx);
        float sum = e0 + e1;
#pragma unroll
        for (int o = 16; o; o >>= 1) sum += __shfl_xor_sync(0xffffffffu, sum, o);
        float inv = 1.f / sum;
        ps[w][lane]      = e0 * inv;
        ps[w][lane + 32] = e1 * inv;
        __syncwarp();

        float acc0 = 0.f, acc1 = 0.f;
#pragma unroll 8
        for (int kk = 0; kk < 64; kk++) {
            float p = ps[w][kk];
            acc0 = fmaf(p, vtile[kk][lane],      acc0);
            acc1 = fmaf(p, vtile[kk][lane + 32], acc1);
        }
        out[obase + j*64 + lane]      = acc0;
        out[obase + j*64 + lane + 32] = acc1;
        __syncwarp();
    }
}

// ---------------------------------------------------------------------------
// out = LayerNorm(X + Y), also writes split bf16
// ---------------------------------------------------------------------------
__global__ void __launch_bounds__(256) k_addln2(const float* __restrict__ X,
                                                const float* __restrict__ Y,
                                                float* __restrict__ out,
                                                __nv_bfloat16* __restrict__ oh,
                                                __nv_bfloat16* __restrict__ ol)
{
    __shared__ float rs[8], rq[8];
    int r = blockIdx.x, t = threadIdx.x;
    size_t base = (size_t)r*512 + t*2;
    float2 xv = *(const float2*)(X + base);
    float2 yv = *(const float2*)(Y + base);
    float v0 = xv.x + yv.x, v1 = xv.y + yv.y;
    float sum = v0 + v1;
    float sq  = v0*v0 + v1*v1;
    int lane = t & 31, w = t >> 5;
#pragma unroll
    for (int o = 16; o; o >>= 1) {
        sum += __shfl_xor_sync(0xffffffffu, sum, o);
        sq  += __shfl_xor_sync(0xffffffffu, sq,  o);
    }
    if (lane == 0) { rs[w] = sum; rq[w] = sq; }
    __syncthreads();
    float ts = 0.f, tq = 0.f;
#pragma unroll
    for (int i = 0; i < 8; i++) { ts += rs[i]; tq += rq[i]; }
    float mu  = ts * (1.f/512.f);
    float var = tq * (1.f/512.f) - mu*mu;
    float inv = 1.f / sqrtf(var + 1e-5f);
    float o0 = (v0 - mu)*inv, o1 = (v1 - mu)*inv;
    *(float2*)(out + base) = make_float2(o0, o1);
    uint32_t hh, ll;
    bsplit2(o0, o1, hh, ll);
    *(uint32_t*)&oh[base] = hh;
    *(uint32_t*)&ol[base] = ll;
}

// ---------------------------------------------------------------------------
// Output projection + softmax: 16 rows/block, W element reused x4
// ---------------------------------------------------------------------------
__global__ void __launch_bounds__(256) k_outproj2(const float* __restrict__ X,
                                                  const float* __restrict__ W,
                                                  const float* __restrict__ b,
                                                  float* __restrict__ out)
{
    __shared__ float xs[16][512];
    __shared__ float lg[16][64];
    int t = threadIdx.x;
    size_t r0 = (size_t)blockIdx.x * 16;

    for (int i = t; i < 2048; i += 256) {
        int idx = i*4, rr = idx >> 9, cc = idx & 511;
        *(float4*)&xs[rr][cc] = *(const float4*)&X[(r0 + rr)*512 + cc];
    }
    __syncthreads();

    int col = t & 63, g = t >> 6;
    float bcol = b[col];
    float a0 = bcol, a1 = bcol, a2 = bcol, a3 = bcol;
#pragma unroll 8
    for (int c = 0; c < 512; c++) {
        float wv = W[c*64 + col];
        a0 = fmaf(xs[g][c],    wv, a0);
        a1 = fmaf(xs[g+4][c],  wv, a1);
        a2 = fmaf(xs[g+8][c],  wv, a2);
        a3 = fmaf(xs[g+12][c], wv, a3);
    }
    lg[g][col]    = a0;
    lg[g+4][col]  = a1;
    lg[g+8][col]  = a2;
    lg[g+12][col] = a3;
    __syncthreads();

    int w8 = t >> 5, lane = t & 31;
#pragma unroll
    for (int rr2 = 0; rr2 < 2; rr2++) {
        int rr = w8*2 + rr2;
        float s0 = lg[rr][lane], s1 = lg[rr][lane + 32];
        float mx = fmaxf(s0, s1);
#pragma unroll
        for (int o = 16; o; o >>= 1) mx = fmaxf(mx, __shfl_xor_sync(~0u, mx, o));
        float e0 = expf(s0 - mx), e1 = expf(s1 - mx);
        float sm = e0 + e1;
#pragma unroll
        for (int o = 16; o; o >>= 1) sm += __shfl_xor_sync(~0u, sm, o);
        float inv = 1.f / sm;
        out[(r0 + rr)*64 + lane]      = e0 * inv;
        out[(r0 + rr)*64 + lane + 32] = e1 * inv;
    }
}

// ---------------------------------------------------------------------------
// Host orchestration
// ---------------------------------------------------------------------------
#define GEMM_SMEM (3*STAGE_BYTES)

extern "C" void kernel_launch(void* const* d_in, const int* in_sizes, int n_in,
                              void* d_out, int out_size)
{
    const float* X_en   = (const float*)d_in[0];
    const float* X_de   = (const float*)d_in[1];
    const float* W_in   = (const float*)d_in[2];
    const float* B_in   = (const float*)d_in[3];
    const float* enc_wq = (const float*)d_in[4];
    const float* enc_wk = (const float*)d_in[5];
    const float* enc_wv = (const float*)d_in[6];
    const float* enc_rel= (const float*)d_in[7];
    const float* enc_w1 = (const float*)d_in[8];
    const float* enc_b1 = (const float*)d_in[9];
    const float* enc_w2 = (const float*)d_in[10];
    const float* enc_b2 = (const float*)d_in[11];
    const float* dec_wq1= (const float*)d_in[12];
    const float* dec_wk1= (const float*)d_in[13];
    const float* dec_wv1= (const float*)d_in[14];
    const float* dec_rel1=(const float*)d_in[15];
    const float* dec_wq2= (const float*)d_in[16];
    const float* dec_wk2= (const float*)d_in[17];
    const float* dec_wv2= (const float*)d_in[18];
    const float* dec_rel2=(const float*)d_in[19];
    const float* dec_w1 = (const float*)d_in[20];
    const float* dec_b1 = (const float*)d_in[21];
    const float* dec_w2 = (const float*)d_in[22];
    const float* dec_b2 = (const float*)d_in[23];
    const float* W_out  = (const float*)d_in[24];
    const float* B_out  = (const float*)d_in[25];
    float* OUT = (float*)d_out;

    static int smem_set = 0;
    if (!smem_set) {
        cudaFuncSetAttribute(k_bgemm, cudaFuncAttributeMaxDynamicSharedMemorySize,
                             GEMM_SMEM);
        smem_set = 1;
    }

    float *xen,*xde,*V,*ATT,*bufA,*bufB,*enc,*ffo,*qs,*ks,*a2,*s1,*wg;
    cudaGetSymbolAddress((void**)&xen,  g_xen);
    cudaGetSymbolAddress((void**)&xde,  g_xde);
    cudaGetSymbolAddress((void**)&V,    g_v);
    cudaGetSymbolAddress((void**)&ATT,  g_attn);
    cudaGetSymbolAddress((void**)&bufA, g_bufA);
    cudaGetSymbolAddress((void**)&bufB, g_bufB);
    cudaGetSymbolAddress((void**)&enc,  g_enc);
    cudaGetSymbolAddress((void**)&ffo,  g_ffo);
    cudaGetSymbolAddress((void**)&qs,   g_qs);
    cudaGetSymbolAddress((void**)&ks,   g_ks);
    cudaGetSymbolAddress((void**)&a2,   g_a2);
    cudaGetSymbolAddress((void**)&s1,   g_s1);
    cudaGetSymbolAddress((void**)&wg,   g_wg);

    __nv_bfloat16 *sxen_h,*sxen_l,*sxde_h,*sxde_l,*xen_h,*xen_l,*xde_h,*xde_l;
    __nv_bfloat16 *enc_h,*enc_l,*bufA_h,*bufA_l,*bufB_h,*bufB_l,*ffh_h,*ffh_l;
    __nv_bfloat16 *win_h,*win_l,*wsp_h,*wsp_l;
    cudaGetSymbolAddress((void**)&sxen_h, g_sxen_h);
    cudaGetSymbolAddress((void**)&sxen_l, g_sxen_l);
    cudaGetSymbolAddress((void**)&sxde_h, g_sxde_h);
    cudaGetSymbolAddress((void**)&sxde_l, g_sxde_l);
    cudaGetSymbolAddress((void**)&xen_h,  g_xen_h);
    cudaGetSymbolAddress((void**)&xen_l,  g_xen_l);
    cudaGetSymbolAddress((void**)&xde_h,  g_xde_h);
    cudaGetSymbolAddress((void**)&xde_l,  g_xde_l);
    cudaGetSymbolAddress((void**)&enc_h,  g_enc_h);
    cudaGetSymbolAddress((void**)&enc_l,  g_enc_l);
    cudaGetSymbolAddress((void**)&bufA_h, g_bufA_h);
    cudaGetSymbolAddress((void**)&bufA_l, g_bufA_l);
    cudaGetSymbolAddress((void**)&bufB_h, g_bufB_h);
    cudaGetSymbolAddress((void**)&bufB_l, g_bufB_l);
    cudaGetSymbolAddress((void**)&ffh_h,  g_ffh_h);
    cudaGetSymbolAddress((void**)&ffh_l,  g_ffh_l);
    cudaGetSymbolAddress((void**)&win_h,  g_win_h);
    cudaGetSymbolAddress((void**)&win_l,  g_win_l);
    cudaGetSymbolAddress((void**)&wsp_h,  g_wsp_h);
    cudaGetSymbolAddress((void**)&wsp_l,  g_wsp_l);

    // ---- split weights & raw inputs ----
    k_split<<<4096, 256>>>(X_en, sxen_h, sxen_l, 4194304);
    k_split<<<4096, 256>>>(X_de, sxde_h, sxde_l, 4194304);
    k_split<<<32,   256>>>(W_in, win_h, win_l, 32768);
    k_split<<<256,  256>>>(enc_wv,  wsp_h + WV0, wsp_l + WV0, 262144);
    k_split<<<256,  256>>>(dec_wv1, wsp_h + WV1, wsp_l + WV1, 262144);
    k_split<<<256,  256>>>(dec_wv2, wsp_h + WV2, wsp_l + WV2, 262144);
    k_split<<<1024, 256>>>(enc_w1,  wsp_h + W1E, wsp_l + W1E, 1048576);
    k_split<<<1024, 256>>>(enc_w2,  wsp_h + W2E, wsp_l + W2E, 1048576);
    k_split<<<1024, 256>>>(dec_w1,  wsp_h + W1D, wsp_l + W1D, 1048576);
    k_split<<<1024, 256>>>(dec_w2,  wsp_h + W2D, wsp_l + W2D, 1048576);
    k_wsum6<<<96, 256>>>(enc_wq, enc_wk, dec_wq1, dec_wk1, dec_wq2, dec_wk2, wg);

    dim3 g512(4,128), g2048(16,128);

    // ---- embeddings ----
    k_bgemm<<<g512, 256, GEMM_SMEM>>>(sxen_h, sxen_l, win_h, win_l, B_in,
                                      xen, xen_h, xen_l, NROW, 512, 64, 1|4);
    k_bgemm<<<g512, 256, GEMM_SMEM>>>(sxde_h, sxde_l, win_h, win_l, B_in,
                                      xde, xde_h, xde_l, NROW, 512, 64, 1|4);

    // ---- encoder ----
    k_bgemm<<<g512, 256, GEMM_SMEM>>>(xen_h, xen_l, wsp_h + WV0, wsp_l + WV0,
                                      nullptr, V, nullptr, nullptr,
                                      NROW, 512, 512, 0);
    k_qks<<<2048, 256>>>(xen, xen, wg + 0*4096, wg + 1*4096, qs, ks);
    k_attn_prep<<<LLEN*HN, 256>>>(enc_rel, ks, a2, s1);
    k_attn_out<<<LLEN*HN, 256>>>(V, qs, a2, s1, ATT, 0);
    k_addln2<<<NROW, 256>>>(xen, ATT, bufA, bufA_h, bufA_l);
    k_bgemm<<<g2048, 256, GEMM_SMEM>>>(bufA_h, bufA_l, wsp_h + W1E, wsp_l + W1E,
                                       enc_b1, nullptr, ffh_h, ffh_l,
                                       NROW, DFF, 512, 1|2|4|8);
    k_bgemm<<<g512, 256, GEMM_SMEM>>>(ffh_h, ffh_l, wsp_h + W2E, wsp_l + W2E,
                                      enc_b2, ffo, nullptr, nullptr,
                                      NROW, 512, DFF, 1);
    k_addln2<<<NROW, 256>>>(bufA, ffo, enc, enc_h, enc_l);

    // ---- decoder self-attn (causal) ----
    k_bgemm<<<g512, 256, GEMM_SMEM>>>(xde_h, xde_l, wsp_h + WV1, wsp_l + WV1,
                                      nullptr, V, nullptr, nullptr,
                                      NROW, 512, 512, 0);
    k_qks<<<2048, 256>>>(xde, xde, wg + 2*4096, wg + 3*4096, qs, ks);
    k_attn_prep<<<LLEN*HN, 256>>>(dec_rel1, ks, a2, s1);
    k_attn_out<<<LLEN*HN, 256>>>(V, qs, a2, s1, ATT, 1);
    k_addln2<<<NROW, 256>>>(xde, ATT, bufA, bufA_h, bufA_l);   // m

    // ---- decoder cross-attn ----
    k_bgemm<<<g512, 256, GEMM_SMEM>>>(enc_h, enc_l, wsp_h + WV2, wsp_l + WV2,
                                      nullptr, V, nullptr, nullptr,
                                      NROW, 512, 512, 0);
    k_qks<<<2048, 256>>>(bufA, enc, wg + 4*4096, wg + 5*4096, qs, ks);
    k_attn_prep<<<LLEN*HN, 256>>>(dec_rel2, ks, a2, s1);
    k_attn_out<<<LLEN*HN, 256>>>(V, qs, a2, s1, ATT, 0);
    k_addln2<<<NROW, 256>>>(ATT, bufA, bufB, bufB_h, bufB_l);  // c

    // ---- decoder FFN ----
    k_bgemm<<<g2048, 256, GEMM_SMEM>>>(bufB_h, bufB_l, wsp_h + W1D, wsp_l + W1D,
                                       dec_b1, nullptr, ffh_h, ffh_l,
                                       NROW, DFF, 512, 1|2|4|8);
    k_bgemm<<<g512, 256, GEMM_SMEM>>>(ffh_h, ffh_l, wsp_h + W2D, wsp_l + W2D,
                                      dec_b2, ffo, nullptr, nullptr,
                                      NROW, 512, DFF, 1);
    k_addln2<<<NROW, 256>>>(bufB, ffo, bufA, bufA_h, bufA_l);

    // ---- output projection + softmax ----
    k_outproj2<<<1024, 256>>>(bufA, W_out, B_out, OUT);

    (void)in_sizes; (void)n_in; (void)out_size;
}

// round 8
// speedup vs baseline: 3.1501x; 1.1229x over previous
#include <cuda_runtime.h>
#include <cuda_bf16.h>
#include <math.h>
#include <stdint.h>

// ---------------------------------------------------------------------------
// Problem constants
// ---------------------------------------------------------------------------
#define NROW  16384
#define DMODEL 512
#define DFF   2048
#define LLEN  256
#define HN    8
#define NSEG  (NROW*8)
#define SC2   (1.0f/64.0f)

// ---------------------------------------------------------------------------
// Scratch (fp32)
// ---------------------------------------------------------------------------
__device__ float g_xen [NROW*DMODEL];
__device__ float g_xde [NROW*DMODEL];
__device__ float g_v   [NROW*DMODEL];
__device__ float g_attn[NROW*DMODEL];
__device__ float g_bufA[NROW*DMODEL];
__device__ float g_bufB[NROW*DMODEL];
__device__ float g_enc [NROW*DMODEL];
__device__ float g_ffo [NROW*DMODEL];
__device__ float g_qs  [NSEG];
__device__ float g_ks  [NSEG];
__device__ float g_a2  [LLEN*HN*64];
__device__ float g_s1  [LLEN*HN];
__device__ float g_wg  [6*8*512];

// Split bf16 buffers (hi/lo)
__device__ __nv_bfloat16 g_sxen_h[4194304], g_sxen_l[4194304];
__device__ __nv_bfloat16 g_sxde_h[4194304], g_sxde_l[4194304];
__device__ __nv_bfloat16 g_xen_h [NROW*DMODEL], g_xen_l [NROW*DMODEL];
__device__ __nv_bfloat16 g_xde_h [NROW*DMODEL], g_xde_l [NROW*DMODEL];
__device__ __nv_bfloat16 g_enc_h [NROW*DMODEL], g_enc_l [NROW*DMODEL];
__device__ __nv_bfloat16 g_bufA_h[NROW*DMODEL], g_bufA_l[NROW*DMODEL];
__device__ __nv_bfloat16 g_bufB_h[NROW*DMODEL], g_bufB_l[NROW*DMODEL];
__device__ __nv_bfloat16 g_ffh_h [NROW*DFF],    g_ffh_l [NROW*DFF];
__device__ __nv_bfloat16 g_win_h [32768],       g_win_l [32768];
#define NWSPLIT 4980736
__device__ __nv_bfloat16 g_wsp_h[NWSPLIT], g_wsp_l[NWSPLIT];
#define WV0 0
#define WV1 262144
#define WV2 524288
#define W1E 786432
#define W2E 1835008
#define W1D 2883584
#define W2D 3932160

// ---------------------------------------------------------------------------
// Helpers
// ---------------------------------------------------------------------------
__device__ __forceinline__ uint32_t smem_u32(const void* p) {
    return (uint32_t)__cvta_generic_to_shared(p);
}
__device__ __forceinline__ void ldsm_x4(uint32_t* r, uint32_t addr) {
    asm volatile("ldmatrix.sync.aligned.m8n8.x4.shared.b16 {%0,%1,%2,%3}, [%4];"
        : "=r"(r[0]), "=r"(r[1]), "=r"(r[2]), "=r"(r[3]) : "r"(addr));
}
__device__ __forceinline__ void ldsm_x4t(uint32_t* r, uint32_t addr) {
    asm volatile("ldmatrix.sync.aligned.m8n8.x4.trans.shared.b16 {%0,%1,%2,%3}, [%4];"
        : "=r"(r[0]), "=r"(r[1]), "=r"(r[2]), "=r"(r[3]) : "r"(addr));
}
__device__ __forceinline__ void mma_bf16(float* c, const uint32_t* a, const uint32_t* b) {
    asm volatile(
        "mma.sync.aligned.m16n8k16.row.col.f32.bf16.bf16.f32 "
        "{%0,%1,%2,%3},{%4,%5,%6,%7},{%8,%9},{%0,%1,%2,%3};"
        : "+f"(c[0]), "+f"(c[1]), "+f"(c[2]), "+f"(c[3])
        : "r"(a[0]), "r"(a[1]), "r"(a[2]), "r"(a[3]), "r"(b[0]), "r"(b[1]));
}
__device__ __forceinline__ void cp16(uint32_t dst, const void* src) {
    asm volatile("cp.async.cg.shared.global [%0], [%1], 16;" :: "r"(dst), "l"(src));
}
__device__ __forceinline__ void cp_commit() {
    asm volatile("cp.async.commit_group;");
}
template<int N> __device__ __forceinline__ void cp_wait() {
    asm volatile("cp.async.wait_group %0;" :: "n"(N));
}
__device__ __forceinline__ void bsplit(float x, unsigned short& h, unsigned short& l) {
    __nv_bfloat16 hb = __float2bfloat16(x);
    float r = x - __bfloat162float(hb);
    h = __bfloat16_as_ushort(hb);
    l = __bfloat16_as_ushort(__float2bfloat16(r));
}
__device__ __forceinline__ void bsplit2(float a, float b, uint32_t& hh, uint32_t& ll) {
    unsigned short h0,l0,h1,l1;
    bsplit(a,h0,l0); bsplit(b,h1,l1);
    hh = (uint32_t)h0 | ((uint32_t)h1 << 16);
    ll = (uint32_t)l0 | ((uint32_t)l1 << 16);
}

// ---------------------------------------------------------------------------
// k_split: fp32 -> (hi,lo) bf16
// ---------------------------------------------------------------------------
__global__ void __launch_bounds__(256) k_split(const float* __restrict__ x,
                                               __nv_bfloat16* __restrict__ hi,
                                               __nv_bfloat16* __restrict__ lo,
                                               int n)
{
    int i = (blockIdx.x*256 + threadIdx.x)*4;
    if (i >= n) return;
    float4 v = *(const float4*)(x + i);
    uint32_t h0,l0,h1,l1;
    bsplit2(v.x, v.y, h0, l0);
    bsplit2(v.z, v.w, h1, l1);
    *(uint2*)&hi[i] = make_uint2(h0, h1);
    *(uint2*)&lo[i] = make_uint2(l0, l1);
}

// ---------------------------------------------------------------------------
// Pipelined split-bf16 tensor GEMM (3 passes), 2 CTAs/SM.
// A = Ah+Al [M,K] row-major; B = Bh+Bl [K,N] row-major.
// Tile 128x128x32, 256 threads, warps 2(m)x4(n), 3-stage cp.async pipeline.
// flags: b0 bias, b1 relu, b2 write split (Ch,Cl), b3 skip fp32 C.
// ---------------------------------------------------------------------------
#define STAGE_BYTES 36864
#define OFF_AL 10240
#define OFF_BH 20480
#define OFF_BL 28672
#define GEMM_SMEM (3*STAGE_BYTES)

extern __shared__ char dsm[];

__device__ __forceinline__ void ld_stage(uint32_t sb,
    const __nv_bfloat16* __restrict__ Ah, const __nv_bfloat16* __restrict__ Al,
    const __nv_bfloat16* __restrict__ Bh, const __nv_bfloat16* __restrict__ Bl,
    int K, int N, int bm, int bn, int tid, int k0)
{
    int rowA = tid >> 2, kc = tid & 3;
    size_t aoff0 = (size_t)(bm + rowA)*K + k0 + kc*8;
    size_t aoff1 = aoff0 + (size_t)64*K;
    uint32_t dA = sb + rowA*80 + kc*16;
    cp16(dA,            Ah + aoff0);
    cp16(dA + 64*80,    Ah + aoff1);
    cp16(dA + OFF_AL,         Al + aoff0);
    cp16(dA + OFF_AL + 64*80, Al + aoff1);

    int kr = tid >> 4, nc = tid & 15;
    size_t boff0 = (size_t)(k0 + kr)*N + bn + nc*8;
    size_t boff1 = boff0 + (size_t)16*N;
    uint32_t dB0 = sb + OFF_BH + kr*256 + ((nc ^ (kr & 7)) << 4);
    uint32_t dB1 = sb + OFF_BH + (kr+16)*256 + ((nc ^ ((kr+16) & 7)) << 4);
    cp16(dB0, Bh + boff0);
    cp16(dB1, Bh + boff1);
    cp16(dB0 + 8192, Bl + boff0);
    cp16(dB1 + 8192, Bl + boff1);
}

__global__ void __launch_bounds__(256, 2) k_bgemm(
    const __nv_bfloat16* __restrict__ Ah, const __nv_bfloat16* __restrict__ Al,
    const __nv_bfloat16* __restrict__ Bh, const __nv_bfloat16* __restrict__ Bl,
    const float* __restrict__ bias, float* __restrict__ C,
    __nv_bfloat16* __restrict__ Ch, __nv_bfloat16* __restrict__ Cl,
    int M, int N, int K, int flags)
{
    const int tid = threadIdx.x;
    const int bm = blockIdx.y * 128;
    const int bn = blockIdx.x * 128;
    const int w = tid >> 5, lane = tid & 31;
    const int wm = (w >> 2) * 64;
    const int wn = (w & 3) * 32;
    const int g = lane >> 2, tg = lane & 3;
    const uint32_t sbase = smem_u32(dsm);

    float acc[4][4][4];
#pragma unroll
    for (int mf = 0; mf < 4; mf++)
#pragma unroll
        for (int nf = 0; nf < 4; nf++)
#pragma unroll
            for (int i = 0; i < 4; i++) acc[mf][nf][i] = 0.f;

    const int a_off0 = (wm + (lane & 15))*40 + (lane >> 4)*8;
    const int bkl  = (lane & 7) + ((lane >> 3) & 1)*8;
    const int bncl = lane >> 4;

    const int T = K / 32;

    ld_stage(sbase,               Ah, Al, Bh, Bl, K, N, bm, bn, tid, 0);
    cp_commit();
    ld_stage(sbase + STAGE_BYTES, Ah, Al, Bh, Bl, K, N, bm, bn, tid, 32);
    cp_commit();

    for (int kt = 0; kt < T; ++kt) {
        cp_wait<1>();
        __syncthreads();

        if (kt + 2 < T) {
            int buf = (kt + 2) % 3;
            ld_stage(sbase + buf*STAGE_BYTES, Ah, Al, Bh, Bl, K, N, bm, bn,
                     tid, (kt + 2)*32);
        }
        cp_commit();

        const uint32_t bA = sbase + (kt % 3)*STAGE_BYTES;
        const uint32_t bB = bA + OFF_BH;
#pragma unroll
        for (int ks2 = 0; ks2 < 32; ks2 += 16) {
            uint32_t ah[4][4], al[4][4];
#pragma unroll
            for (int mf = 0; mf < 4; mf++) {
                int eoff = a_off0 + mf*640 + ks2;
                ldsm_x4(ah[mf], bA + 2*eoff);
                ldsm_x4(al[mf], bA + OFF_AL + 2*eoff);
            }
            uint32_t bh[4][2], bl[4][2];
#pragma unroll
            for (int nf2 = 0; nf2 < 2; nf2++) {
                int k = ks2 + bkl;
                int nc = (wn >> 3) + nf2*2 + bncl;
                int eoff = k*128 + ((nc ^ (k & 7)) << 3);
                uint32_t r[4];
                ldsm_x4t(r, bB + 2*eoff);
                bh[nf2*2][0] = r[0]; bh[nf2*2][1] = r[1];
                bh[nf2*2+1][0] = r[2]; bh[nf2*2+1][1] = r[3];
                ldsm_x4t(r, bB + 8192 + 2*eoff);
                bl[nf2*2][0] = r[0]; bl[nf2*2][1] = r[1];
                bl[nf2*2+1][0] = r[2]; bl[nf2*2+1][1] = r[3];
            }
#pragma unroll
            for (int mf = 0; mf < 4; mf++)
#pragma unroll
                for (int nf = 0; nf < 4; nf++) {
                    mma_bf16(acc[mf][nf], ah[mf], bh[nf]);
                    mma_bf16(acc[mf][nf], al[mf], bh[nf]);
                    mma_bf16(acc[mf][nf], ah[mf], bl[nf]);
                }
        }
    }

    // epilogue
#pragma unroll
    for (int mf = 0; mf < 4; mf++) {
#pragma unroll
        for (int nf = 0; nf < 4; nf++) {
            int row = bm + wm + mf*16 + g;
            int col = bn + wn + nf*8 + tg*2;
            float o0 = acc[mf][nf][0], o1 = acc[mf][nf][1];
            float o2 = acc[mf][nf][2], o3 = acc[mf][nf][3];
            if (flags & 1) {
                float b0 = bias[col], b1 = bias[col+1];
                o0 += b0; o1 += b1; o2 += b0; o3 += b1;
            }
            if (flags & 2) {
                o0 = fmaxf(o0,0.f); o1 = fmaxf(o1,0.f);
                o2 = fmaxf(o2,0.f); o3 = fmaxf(o3,0.f);
            }
            size_t i0 = (size_t)row*N + col;
            size_t i1 = (size_t)(row+8)*N + col;
            if (!(flags & 8)) {
                *(float2*)&C[i0] = make_float2(o0, o1);
                *(float2*)&C[i1] = make_float2(o2, o3);
            }
            if (flags & 4) {
                uint32_t hh, ll;
                bsplit2(o0, o1, hh, ll);
                *(uint32_t*)&Ch[i0] = hh;
                *(uint32_t*)&Cl[i0] = ll;
                bsplit2(o2, o3, hh, ll);
                *(uint32_t*)&Ch[i1] = hh;
                *(uint32_t*)&Cl[i1] = ll;
            }
        }
    }
}

// ---------------------------------------------------------------------------
// Weight group-sums (6 q/k matrices)
// ---------------------------------------------------------------------------
__global__ void __launch_bounds__(256) k_wsum6(const float* __restrict__ w0,
                                               const float* __restrict__ w1,
                                               const float* __restrict__ w2,
                                               const float* __restrict__ w3,
                                               const float* __restrict__ w4,
                                               const float* __restrict__ w5,
                                               float* __restrict__ wgT)
{
    int idx = blockIdx.x*256 + threadIdx.x;
    int m = idx >> 12;
    int r = idx & 4095;
    int g = r >> 9, c = r & 511;
    const float* w = (m == 0) ? w0 : (m == 1) ? w1 : (m == 2) ? w2 :
                     (m == 3) ? w3 : (m == 4) ? w4 : w5;
    const float* p = w + (size_t)c*512 + g*64;
    float s = 0.f;
#pragma unroll 16
    for (int j = 0; j < 64; j++) s += p[j];
    wgT[m*4096 + g*512 + c] = s;
}

// ---------------------------------------------------------------------------
// qs/ks
// ---------------------------------------------------------------------------
__global__ void __launch_bounds__(256) k_qks(const float* __restrict__ xq,
                                             const float* __restrict__ xk,
                                             const float* __restrict__ wgq,
                                             const float* __restrict__ wgk,
                                             float* __restrict__ qs,
                                             float* __restrict__ ks)
{
    __shared__ float sq[8][512];
    __shared__ float sk[8][512];
    int t = threadIdx.x;
    for (int i = t; i < 4096; i += 256) {
        sq[i >> 9][i & 511] = wgq[i];
        sk[i >> 9][i & 511] = wgk[i];
    }
    __syncthreads();

    int w = t >> 5, lane = t & 31;
    int r = blockIdx.x*8 + w;
    const float* xqr = xq + (size_t)r*512;
    const float* xkr = xk + (size_t)r*512;

    float aq0=0,aq1=0,aq2=0,aq3=0,aq4=0,aq5=0,aq6=0,aq7=0;
    float ak0=0,ak1=0,ak2=0,ak3=0,ak4=0,ak5=0,ak6=0,ak7=0;
#pragma unroll 4
    for (int i = 0; i < 16; i++) {
        int c = lane + 32*i;
        float xv = xqr[c];
        float kv = xkr[c];
        aq0 = fmaf(xv, sq[0][c], aq0);  ak0 = fmaf(kv, sk[0][c], ak0);
        aq1 = fmaf(xv, sq[1][c], aq1);  ak1 = fmaf(kv, sk[1][c], ak1);
        aq2 = fmaf(xv, sq[2][c], aq2);  ak2 = fmaf(kv, sk[2][c], ak2);
        aq3 = fmaf(xv, sq[3][c], aq3);  ak3 = fmaf(kv, sk[3][c], ak3);
        aq4 = fmaf(xv, sq[4][c], aq4);  ak4 = fmaf(kv, sk[4][c], ak4);
        aq5 = fmaf(xv, sq[5][c], aq5);  ak5 = fmaf(kv, sk[5][c], ak5);
        aq6 = fmaf(xv, sq[6][c], aq6);  ak6 = fmaf(kv, sk[6][c], ak6);
        aq7 = fmaf(xv, sq[7][c], aq7);  ak7 = fmaf(kv, sk[7][c], ak7);
    }
#pragma unroll
    for (int o = 16; o; o >>= 1) {
        aq0 += __shfl_xor_sync(~0u, aq0, o);  ak0 += __shfl_xor_sync(~0u, ak0, o);
        aq1 += __shfl_xor_sync(~0u, aq1, o);  ak1 += __shfl_xor_sync(~0u, ak1, o);
        aq2 += __shfl_xor_sync(~0u, aq2, o);  ak2 += __shfl_xor_sync(~0u, ak2, o);
        aq3 += __shfl_xor_sync(~0u, aq3, o);  ak3 += __shfl_xor_sync(~0u, ak3, o);
        aq4 += __shfl_xor_sync(~0u, aq4, o);  ak4 += __shfl_xor_sync(~0u, ak4, o);
        aq5 += __shfl_xor_sync(~0u, aq5, o);  ak5 += __shfl_xor_sync(~0u, ak5, o);
        aq6 += __shfl_xor_sync(~0u, aq6, o);  ak6 += __shfl_xor_sync(~0u, ak6, o);
        aq7 += __shfl_xor_sync(~0u, aq7, o);  ak7 += __shfl_xor_sync(~0u, ak7, o);
    }
    if (lane == 0) {
        float* q = qs + r*8;
        q[0]=aq0; q[1]=aq1; q[2]=aq2; q[3]=aq3; q[4]=aq4; q[5]=aq5; q[6]=aq6; q[7]=aq7;
    } else if (lane == 1) {
        float* k = ks + r*8;
        k[0]=ak0; k[1]=ak1; k[2]=ak2; k[3]=ak3; k[4]=ak4; k[5]=ak5; k[6]=ak6; k[7]=ak7;
    }
}

// ---------------------------------------------------------------------------
// Attention prep
// ---------------------------------------------------------------------------
__global__ void __launch_bounds__(256) k_attn_prep(const float* __restrict__ rel,
                                                   const float* __restrict__ ks,
                                                   float* __restrict__ A2,
                                                   float* __restrict__ S1)
{
    __shared__ float tile[4096];
    __shared__ float kss[64];
    __shared__ float a1p[64][4];
    __shared__ float a2p[64][4];

    int lh = blockIdx.x;
    int l  = lh >> 3, h = lh & 7;
    int t  = threadIdx.x;

    const float* rp = rel + (size_t)lh*4096;
    for (int i = t; i < 4096; i += 256) tile[i] = rp[i];
    if (t < 64) kss[t] = ks[(l << 9) + (t << 3) + h];
    __syncthreads();

    int kk = t & 63, q = t >> 6;
    float a1 = 0.f, a2 = 0.f;
    int base = 127*kk + 63;
    for (int m = q*16; m < q*16 + 16; m++) {
        int p = base + m;
        int c = p & 127;
        if (c < 64) {
            float a = tile[((p >> 7) << 6) + c];
            float km = kss[m];
            a1 = fmaf(km, a, a1);
            a2 = fmaf(km - 1e9f*(float)m, a, a2);
        }
    }
    a1p[kk][q] = a1;
    a2p[kk][q] = a2;
    __syncthreads();

    if (t < 64) {
        float A1v = a1p[t][0] + a1p[t][1] + a1p[t][2] + a1p[t][3];
        float A2v = a2p[t][0] + a2p[t][1] + a2p[t][2] + a2p[t][3];
        A2[lh*64 + t] = A2v;
        a1p[t][0] = A1v;
    }
    __syncthreads();
    if (t == 0) {
        float s = 0.f;
        for (int i = 0; i < 64; i++) s += a1p[i][0];
        S1[lh] = s;
    }
}

// ---------------------------------------------------------------------------
// Attention softmax + PV
// ---------------------------------------------------------------------------
__global__ void __launch_bounds__(256) k_attn_out(const float* __restrict__ Yv,
                                                  const float* __restrict__ qs,
                                                  const float* __restrict__ A2,
                                                  const float* __restrict__ S1,
                                                  float* __restrict__ out,
                                                  int causal)
{
    __shared__ float vtile[64][64];
    __shared__ float a2s[64];
    __shared__ float qss[64];
    __shared__ float ps[8][64];

    int lh = blockIdx.x;
    int l = lh >> 3, h = lh & 7;
    int t = threadIdx.x, w = t >> 5, lane = t & 31;

    const float* vbase = Yv + (size_t)l*32768 + h*64;
    for (int i = t; i < 4096; i += 256) {
        int kk = i >> 6, n = i & 63;
        vtile[kk][n] = vbase[(size_t)kk*512 + n];
    }
    if (t < 64) {
        a2s[t] = A2[lh*64 + t];
        qss[t] = qs[(l << 9) + (t << 3) + h];
    }
    __syncthreads();

    float cb = SC2 * S1[lh];
    size_t obase = (size_t)l*32768 + (size_t)h*4096;

    for (int j = w; j < 64; j += 8) {
        float cj = cb * qss[j];
        float s0 = cj * a2s[lane];
        float s1 = cj * a2s[lane + 32];
        if (causal) {
            if (lane > j)      s0 += -1e9f;
            if (lane + 32 > j) s1 += -1e9f;
        }
        float mx = fmaxf(s0, s1);
#pragma unroll
        for (int o = 16; o; o >>= 1) mx = fmaxf(mx, __shfl_xor_sync(0xffffffffu, mx, o));
        float e0 = expf(s0 - mx), e1 = expf(s1 - mx);
        float sum = e0 + e1;
#pragma unroll
        for (int o = 16; o; o >>= 1) sum += __shfl_xor_sync(0xffffffffu, sum, o);
        float inv = 1.f / sum;
        ps[w][lane]      = e0 * inv;
        ps[w][lane + 32] = e1 * inv;
        __syncwarp();

        float acc0 = 0.f, acc1 = 0.f;
#pragma unroll 8
        for (int kk = 0; kk < 64; kk++) {
            float p = ps[w][kk];
            acc0 = fmaf(p, vtile[kk][lane],      acc0);
            acc1 = fmaf(p, vtile[kk][lane + 32], acc1);
        }
        out[obase + j*64 + lane]      = acc0;
        out[obase + j*64 + lane + 32] = acc1;
        __syncwarp();
    }
}

// ---------------------------------------------------------------------------
// out = LayerNorm(X + Y), also writes split bf16
// ---------------------------------------------------------------------------
__global__ void __launch_bounds__(256) k_addln2(const float* __restrict__ X,
                                                const float* __restrict__ Y,
                                                float* __restrict__ out,
                                                __nv_bfloat16* __restrict__ oh,
                                                __nv_bfloat16* __restrict__ ol)
{
    __shared__ float rs[8], rq[8];
    int r = blockIdx.x, t = threadIdx.x;
    size_t base = (size_t)r*512 + t*2;
    float2 xv = *(const float2*)(X + base);
    float2 yv = *(const float2*)(Y + base);
    float v0 = xv.x + yv.x, v1 = xv.y + yv.y;
    float sum = v0 + v1;
    float sq  = v0*v0 + v1*v1;
    int lane = t & 31, w = t >> 5;
#pragma unroll
    for (int o = 16; o; o >>= 1) {
        sum += __shfl_xor_sync(0xffffffffu, sum, o);
        sq  += __shfl_xor_sync(0xffffffffu, sq,  o);
    }
    if (lane == 0) { rs[w] = sum; rq[w] = sq; }
    __syncthreads();
    float ts = 0.f, tq = 0.f;
#pragma unroll
    for (int i = 0; i < 8; i++) { ts += rs[i]; tq += rq[i]; }
    float mu  = ts * (1.f/512.f);
    float var = tq * (1.f/512.f) - mu*mu;
    float inv = 1.f / sqrtf(var + 1e-5f);
    float o0 = (v0 - mu)*inv, o1 = (v1 - mu)*inv;
    *(float2*)(out + base) = make_float2(o0, o1);
    uint32_t hh, ll;
    bsplit2(o0, o1, hh, ll);
    *(uint32_t*)&oh[base] = hh;
    *(uint32_t*)&ol[base] = ll;
}

// ---------------------------------------------------------------------------
// Output projection + softmax
// ---------------------------------------------------------------------------
__global__ void __launch_bounds__(256) k_outproj2(const float* __restrict__ X,
                                                  const float* __restrict__ W,
                                                  const float* __restrict__ b,
                                                  float* __restrict__ out)
{
    __shared__ float xs[16][512];
    __shared__ float lg[16][64];
    int t = threadIdx.x;
    size_t r0 = (size_t)blockIdx.x * 16;

    for (int i = t; i < 2048; i += 256) {
        int idx = i*4, rr = idx >> 9, cc = idx & 511;
        *(float4*)&xs[rr][cc] = *(const float4*)&X[(r0 + rr)*512 + cc];
    }
    __syncthreads();

    int col = t & 63, g = t >> 6;
    float bcol = b[col];
    float a0 = bcol, a1 = bcol, a2 = bcol, a3 = bcol;
#pragma unroll 8
    for (int c = 0; c < 512; c++) {
        float wv = W[c*64 + col];
        a0 = fmaf(xs[g][c],    wv, a0);
        a1 = fmaf(xs[g+4][c],  wv, a1);
        a2 = fmaf(xs[g+8][c],  wv, a2);
        a3 = fmaf(xs[g+12][c], wv, a3);
    }
    lg[g][col]    = a0;
    lg[g+4][col]  = a1;
    lg[g+8][col]  = a2;
    lg[g+12][col] = a3;
    __syncthreads();

    int w8 = t >> 5, lane = t & 31;
#pragma unroll
    for (int rr2 = 0; rr2 < 2; rr2++) {
        int rr = w8*2 + rr2;
        float s0 = lg[rr][lane], s1 = lg[rr][lane + 32];
        float mx = fmaxf(s0, s1);
#pragma unroll
        for (int o = 16; o; o >>= 1) mx = fmaxf(mx, __shfl_xor_sync(~0u, mx, o));
        float e0 = expf(s0 - mx), e1 = expf(s1 - mx);
        float sm = e0 + e1;
#pragma unroll
        for (int o = 16; o; o >>= 1) sm += __shfl_xor_sync(~0u, sm, o);
        float inv = 1.f / sm;
        out[(r0 + rr)*64 + lane]      = e0 * inv;
        out[(r0 + rr)*64 + lane + 32] = e1 * inv;
    }
}

// ---------------------------------------------------------------------------
// Host orchestration
// ---------------------------------------------------------------------------
extern "C" void kernel_launch(void* const* d_in, const int* in_sizes, int n_in,
                              void* d_out, int out_size)
{
    const float* X_en   = (const float*)d_in[0];
    const float* X_de   = (const float*)d_in[1];
    const float* W_in   = (const float*)d_in[2];
    const float* B_in   = (const float*)d_in[3];
    const float* enc_wq = (const float*)d_in[4];
    const float* enc_wk = (const float*)d_in[5];
    const float* enc_wv = (const float*)d_in[6];
    const float* enc_rel= (const float*)d_in[7];
    const float* enc_w1 = (const float*)d_in[8];
    const float* enc_b1 = (const float*)d_in[9];
    const float* enc_w2 = (const float*)d_in[10];
    const float* enc_b2 = (const float*)d_in[11];
    const float* dec_wq1= (const float*)d_in[12];
    const float* dec_wk1= (const float*)d_in[13];
    const float* dec_wv1= (const float*)d_in[14];
    const float* dec_rel1=(const float*)d_in[15];
    const float* dec_wq2= (const float*)d_in[16];
    const float* dec_wk2= (const float*)d_in[17];
    const float* dec_wv2= (const float*)d_in[18];
    const float* dec_rel2=(const float*)d_in[19];
    const float* dec_w1 = (const float*)d_in[20];
    const float* dec_b1 = (const float*)d_in[21];
    const float* dec_w2 = (const float*)d_in[22];
    const float* dec_b2 = (const float*)d_in[23];
    const float* W_out  = (const float*)d_in[24];
    const float* B_out  = (const float*)d_in[25];
    float* OUT = (float*)d_out;

    static int smem_set = 0;
    if (!smem_set) {
        cudaFuncSetAttribute(k_bgemm, cudaFuncAttributeMaxDynamicSharedMemorySize,
                             GEMM_SMEM);
        smem_set = 1;
    }

    float *xen,*xde,*V,*ATT,*bufA,*bufB,*enc,*ffo,*qs,*ks,*a2,*s1,*wg;
    cudaGetSymbolAddress((void**)&xen,  g_xen);
    cudaGetSymbolAddress((void**)&xde,  g_xde);
    cudaGetSymbolAddress((void**)&V,    g_v);
    cudaGetSymbolAddress((void**)&ATT,  g_attn);
    cudaGetSymbolAddress((void**)&bufA, g_bufA);
    cudaGetSymbolAddress((void**)&bufB, g_bufB);
    cudaGetSymbolAddress((void**)&enc,  g_enc);
    cudaGetSymbolAddress((void**)&ffo,  g_ffo);
    cudaGetSymbolAddress((void**)&qs,   g_qs);
    cudaGetSymbolAddress((void**)&ks,   g_ks);
    cudaGetSymbolAddress((void**)&a2,   g_a2);
    cudaGetSymbolAddress((void**)&s1,   g_s1);
    cudaGetSymbolAddress((void**)&wg,   g_wg);

    __nv_bfloat16 *sxen_h,*sxen_l,*sxde_h,*sxde_l,*xen_h,*xen_l,*xde_h,*xde_l;
    __nv_bfloat16 *enc_h,*enc_l,*bufA_h,*bufA_l,*bufB_h,*bufB_l,*ffh_h,*ffh_l;
    __nv_bfloat16 *win_h,*win_l,*wsp_h,*wsp_l;
    cudaGetSymbolAddress((void**)&sxen_h, g_sxen_h);
    cudaGetSymbolAddress((void**)&sxen_l, g_sxen_l);
    cudaGetSymbolAddress((void**)&sxde_h, g_sxde_h);
    cudaGetSymbolAddress((void**)&sxde_l, g_sxde_l);
    cudaGetSymbolAddress((void**)&xen_h,  g_xen_h);
    cudaGetSymbolAddress((void**)&xen_l,  g_xen_l);
    cudaGetSymbolAddress((void**)&xde_h,  g_xde_h);
    cudaGetSymbolAddress((void**)&xde_l,  g_xde_l);
    cudaGetSymbolAddress((void**)&enc_h,  g_enc_h);
    cudaGetSymbolAddress((void**)&enc_l,  g_enc_l);
    cudaGetSymbolAddress((void**)&bufA_h, g_bufA_h);
    cudaGetSymbolAddress((void**)&bufA_l, g_bufA_l);
    cudaGetSymbolAddress((void**)&bufB_h, g_bufB_h);
    cudaGetSymbolAddress((void**)&bufB_l, g_bufB_l);
    cudaGetSymbolAddress((void**)&ffh_h,  g_ffh_h);
    cudaGetSymbolAddress((void**)&ffh_l,  g_ffh_l);
    cudaGetSymbolAddress((void**)&win_h,  g_win_h);
    cudaGetSymbolAddress((void**)&win_l,  g_win_l);
    cudaGetSymbolAddress((void**)&wsp_h,  g_wsp_h);
    cudaGetSymbolAddress((void**)&wsp_l,  g_wsp_l);

    dim3 g512(4,128), g2048(16,128);

    // Launch order: ncu (-s 5 -c 1) captures launch #6 = V_enc (K=512 GEMM)
    k_split<<<4096, 256>>>(X_en, sxen_h, sxen_l, 4194304);           // 1
    k_split<<<32, 256>>>(W_in, win_h, win_l, 32768);                 // 2
    k_bgemm<<<g512, 256, GEMM_SMEM>>>(sxen_h, sxen_l, win_h, win_l, B_in,
                                      xen, xen_h, xen_l,
                                      NROW, 512, 64, 1|4);           // 3 embed_en
    k_split<<<256, 256>>>(enc_wv, wsp_h + WV0, wsp_l + WV0, 262144); // 4
    k_split<<<4096, 256>>>(X_de, sxde_h, sxde_l, 4194304);           // 5
    k_bgemm<<<g512, 256, GEMM_SMEM>>>(xen_h, xen_l, wsp_h + WV0, wsp_l + WV0,
                                      nullptr, V, nullptr, nullptr,
                                      NROW, 512, 512, 0);            // 6 V_enc (ncu)
    k_bgemm<<<g512, 256, GEMM_SMEM>>>(sxde_h, sxde_l, win_h, win_l, B_in,
                                      xde, xde_h, xde_l,
                                      NROW, 512, 64, 1|4);           // 7 embed_de

    // remaining weight splits + group-sums
    k_split<<<256,  256>>>(dec_wv1, wsp_h + WV1, wsp_l + WV1, 262144);
    k_split<<<256,  256>>>(dec_wv2, wsp_h + WV2, wsp_l + WV2, 262144);
    k_split<<<1024, 256>>>(enc_w1,  wsp_h + W1E, wsp_l + W1E, 1048576);
    k_split<<<1024, 256>>>(enc_w2,  wsp_h + W2E, wsp_l + W2E, 1048576);
    k_split<<<1024, 256>>>(dec_w1,  wsp_h + W1D, wsp_l + W1D, 1048576);
    k_split<<<1024, 256>>>(dec_w2,  wsp_h + W2D, wsp_l + W2D, 1048576);
    k_wsum6<<<96, 256>>>(enc_wq, enc_wk, dec_wq1, dec_wk1, dec_wq2, dec_wk2, wg);

    // ---- encoder ----
    k_qks<<<2048, 256>>>(xen, xen, wg + 0*4096, wg + 1*4096, qs, ks);
    k_attn_prep<<<LLEN*HN, 256>>>(enc_rel, ks, a2, s1);
    k_attn_out<<<LLEN*HN, 256>>>(V, qs, a2, s1, ATT, 0);
    k_addln2<<<NROW, 256>>>(xen, ATT, bufA, bufA_h, bufA_l);
    k_bgemm<<<g2048, 256, GEMM_SMEM>>>(bufA_h, bufA_l, wsp_h + W1E, wsp_l + W1E,
                                       enc_b1, nullptr, ffh_h, ffh_l,
                                       NROW, DFF, 512, 1|2|4|8);
    k_bgemm<<<g512, 256, GEMM_SMEM>>>(ffh_h, ffh_l, wsp_h + W2E, wsp_l + W2E,
                                      enc_b2, ffo, nullptr, nullptr,
                                      NROW, 512, DFF, 1);
    k_addln2<<<NROW, 256>>>(bufA, ffo, enc, enc_h, enc_l);

    // ---- decoder self-attn (causal) ----
    k_bgemm<<<g512, 256, GEMM_SMEM>>>(xde_h, xde_l, wsp_h + WV1, wsp_l + WV1,
                                      nullptr, V, nullptr, nullptr,
                                      NROW, 512, 512, 0);
    k_qks<<<2048, 256>>>(xde, xde, wg + 2*4096, wg + 3*4096, qs, ks);
    k_attn_prep<<<LLEN*HN, 256>>>(dec_rel1, ks, a2, s1);
    k_attn_out<<<LLEN*HN, 256>>>(V, qs, a2, s1, ATT, 1);
    k_addln2<<<NROW, 256>>>(xde, ATT, bufA, bufA_h, bufA_l);   // m

    // ---- decoder cross-attn ----
    k_bgemm<<<g512, 256, GEMM_SMEM>>>(enc_h, enc_l, wsp_h + WV2, wsp_l + WV2,
                                      nullptr, V, nullptr, nullptr,
                                      NROW, 512, 512, 0);
    k_qks<<<2048, 256>>>(bufA, enc, wg + 4*4096, wg + 5*4096, qs, ks);
    k_attn_prep<<<LLEN*HN, 256>>>(dec_rel2, ks, a2, s1);
    k_attn_out<<<LLEN*HN, 256>>>(V, qs, a2, s1, ATT, 0);
    k_addln2<<<NROW, 256>>>(ATT, bufA, bufB, bufB_h, bufB_l);  // c

    // ---- decoder FFN ----
    k_bgemm<<<g2048, 256, GEMM_SMEM>>>(bufB_h, bufB_l, wsp_h + W1D, wsp_l + W1D,
                                       dec_b1, nullptr, ffh_h, ffh_l,
                                       NROW, DFF, 512, 1|2|4|8);
    k_bgemm<<<g512, 256, GEMM_SMEM>>>(ffh_h, ffh_l, wsp_h + W2D, wsp_l + W2D,
                                      dec_b2, ffo, nullptr, nullptr,
                                      NROW, 512, DFF, 1);
    k_addln2<<<NROW, 256>>>(bufB, ffo, bufA, bufA_h, bufA_l);

    // ---- output projection + softmax ----
    k_outproj2<<<1024, 256>>>(bufA, W_out, B_out, OUT);

    (void)in_sizes; (void)n_in; (void)out_size;
}